// round 1
// baseline (speedup 1.0000x reference)
#include <cuda_runtime.h>
#include <math.h>

#define B_   16
#define C_   512
#define NSP  1024     // H*W
#define NG   32
#define GC   16       // channels per group
#define NH   8
#define HD   64

// Scratch (device globals: allowed; no allocations anywhere)
__device__ float g_h  [(size_t)B_ * C_ * NSP];        // 33.5 MB  groupnorm out
__device__ float g_qkv[(size_t)B_ * 3 * C_ * NSP];    // 100 MB   qkv
__device__ float g_ao [(size_t)B_ * C_ * NSP];        // 33.5 MB  attention out

// ---------------------------------------------------------------------------
// GroupNorm: one block per (batch, group). 16 ch x 1024 = 16384 floats/block.
// ---------------------------------------------------------------------------
__global__ __launch_bounds__(256) void gn_kernel(const float* __restrict__ x,
                                                 const float* __restrict__ gamma,
                                                 const float* __restrict__ beta,
                                                 float* __restrict__ hout) {
    int b = blockIdx.x >> 5;
    int g = blockIdx.x & 31;
    const float4* xp = (const float4*)(x    + ((size_t)b * C_ + g * GC) * NSP);
    float4*       hp = (float4*)      (hout + ((size_t)b * C_ + g * GC) * NSP);
    int tid = threadIdx.x;

    float s = 0.f, ss = 0.f;
    for (int i = tid; i < (GC * NSP) / 4; i += 256) {
        float4 v = xp[i];
        s  += v.x + v.y + v.z + v.w;
        ss += v.x * v.x + v.y * v.y + v.z * v.z + v.w * v.w;
    }
    __shared__ float rs[256], rss[256];
    rs[tid] = s; rss[tid] = ss;
    __syncthreads();
    for (int off = 128; off > 0; off >>= 1) {
        if (tid < off) { rs[tid] += rs[tid + off]; rss[tid] += rss[tid + off]; }
        __syncthreads();
    }
    const float invn = 1.f / (GC * NSP);
    float mean = rs[0] * invn;
    float var  = rss[0] * invn - mean * mean;
    float inv  = rsqrtf(var + 1e-5f);

    for (int i = tid; i < (GC * NSP) / 4; i += 256) {
        int cl = i >> 8;                        // (i*4)/1024: channel within group
        float ga = gamma[g * GC + cl] * inv;
        float be = beta [g * GC + cl];
        float4 v = xp[i];
        float4 o;
        o.x = (v.x - mean) * ga + be;
        o.y = (v.y - mean) * ga + be;
        o.z = (v.z - mean) * ga + be;
        o.w = (v.w - mean) * ga + be;
        hp[i] = o;
    }
}

// ---------------------------------------------------------------------------
// Batched SGEMM: Out[b][m][n] = sum_c W[m][c] * Hin[b][c][n] + bias[m] (+X)
// K = 512, N = 1024. Tile 64x64xBK16, 256 threads, 4x4 microtile.
// ---------------------------------------------------------------------------
__global__ __launch_bounds__(256) void gemm_kernel(const float* __restrict__ W,
                                                   const float* __restrict__ Hin,
                                                   const float* __restrict__ bias,
                                                   const float* __restrict__ X,
                                                   float* __restrict__ Out,
                                                   int M) {
    __shared__ float Ws[16][68];   // [k][m], padded (272B row: 16B aligned)
    __shared__ float Hs[16][64];   // [k][n]

    int bz = blockIdx.z;
    const float* Hb = Hin + (size_t)bz * C_ * NSP;
    int m0 = blockIdx.y * 64;
    int n0 = blockIdx.x * 64;
    int tid = threadIdx.x, tx = tid & 15, ty = tid >> 4;

    int wm = tid >> 2;            // 0..63
    int wk = (tid & 3) * 4;       // 0,4,8,12
    int hk = tid >> 4;            // 0..15
    int hn = (tid & 15) * 4;      // 0..60

    float acc[4][4] = {};

    for (int c0 = 0; c0 < C_; c0 += 16) {
        float4 wv = *(const float4*)&W [(size_t)(m0 + wm) * C_  + c0 + wk];
        float4 hv = *(const float4*)&Hb[(size_t)(c0 + hk) * NSP + n0 + hn];
        __syncthreads();
        Ws[wk + 0][wm] = wv.x;
        Ws[wk + 1][wm] = wv.y;
        Ws[wk + 2][wm] = wv.z;
        Ws[wk + 3][wm] = wv.w;
        *(float4*)&Hs[hk][hn] = hv;
        __syncthreads();
        #pragma unroll
        for (int k = 0; k < 16; k++) {
            float4 av = *(float4*)&Ws[k][ty * 4];
            float4 bv = *(float4*)&Hs[k][tx * 4];
            float a[4] = {av.x, av.y, av.z, av.w};
            float b[4] = {bv.x, bv.y, bv.z, bv.w};
            #pragma unroll
            for (int i = 0; i < 4; i++)
                #pragma unroll
                for (int j = 0; j < 4; j++)
                    acc[i][j] = fmaf(a[i], b[j], acc[i][j]);
        }
    }

    float*       Ob = Out + (size_t)bz * M * NSP;
    const float* Xb = X ? (X + (size_t)bz * M * NSP) : nullptr;
    #pragma unroll
    for (int i = 0; i < 4; i++) {
        int m = m0 + ty * 4 + i;
        float bv = bias[m];
        size_t idx = (size_t)m * NSP + n0 + tx * 4;
        float4 o = {acc[i][0] + bv, acc[i][1] + bv, acc[i][2] + bv, acc[i][3] + bv};
        if (Xb) {
            float4 xv = *(const float4*)&Xb[idx];
            o.x += xv.x; o.y += xv.y; o.z += xv.z; o.w += xv.w;
        }
        *(float4*)&Ob[idx] = o;
    }
}

// ---------------------------------------------------------------------------
// Fused flash-style attention. One block per (q-tile of 64, head, batch).
// qkv layout: [b][3*512][1024]; q at head*64, k at 512+head*64, v at 1024+head*64.
// S = (Q^T K)/8, online softmax over keys, O[nq][dd] = sum_m P[nq][m] V[dd][m].
// ---------------------------------------------------------------------------
#define ATTN_SMEM ((4096 + 4096 + 64*68 + 64*65 + 192) * 4)

__global__ __launch_bounds__(256) void attn_kernel(const float* __restrict__ qkv,
                                                   float* __restrict__ ao) {
    extern __shared__ float smf[];
    float* Qs     = smf;                    // [dd][nq]  64x64
    float* Ks     = smf + 4096;             // [dd][mk]  64x64
    float* Vst    = smf + 8192;             // [mk][dd]  64x68 (transposed, padded)
    float* Ss     = smf + 8192 + 64 * 68;   // [nq][mk]  64x65
    float* rowmax = Ss + 64 * 65;
    float* rowsum = rowmax + 64;
    float* corrs  = rowsum + 64;

    int qt = blockIdx.x, hh = blockIdx.y, b = blockIdx.z;
    const float* qb = qkv + ((size_t)b * (3 * C_) + hh * HD) * NSP;
    const float* kb = qb + (size_t)C_ * NSP;
    const float* vb = qb + (size_t)2 * C_ * NSP;
    int n0 = qt * 64;
    int tid = threadIdx.x, tx = tid & 15, ty = tid >> 4;

    // Load Q tile [dd][nq]
    #pragma unroll
    for (int r = 0; r < 4; r++) {
        int dd = r * 16 + (tid >> 4);
        int n4 = (tid & 15) * 4;
        *(float4*)&Qs[dd * 64 + n4] = *(const float4*)&qb[(size_t)dd * NSP + n0 + n4];
    }
    if (tid < 64) { rowmax[tid] = -INFINITY; rowsum[tid] = 0.f; }

    float o[4][4] = {};   // [nq_i][dd_j]

    for (int kt = 0; kt < 16; kt++) {
        int m0 = kt * 64;
        __syncthreads();   // Q visible / previous GEMM2 reads done
        #pragma unroll
        for (int r = 0; r < 4; r++) {
            int dd = r * 16 + (tid >> 4);
            int m4 = (tid & 15) * 4;
            *(float4*)&Ks[dd * 64 + m4] = *(const float4*)&kb[(size_t)dd * NSP + m0 + m4];
            float4 v = *(const float4*)&vb[(size_t)dd * NSP + m0 + m4];
            Vst[(m4 + 0) * 68 + dd] = v.x;
            Vst[(m4 + 1) * 68 + dd] = v.y;
            Vst[(m4 + 2) * 68 + dd] = v.z;
            Vst[(m4 + 3) * 68 + dd] = v.w;
        }
        __syncthreads();

        // GEMM1: S[nq][mk] = sum_dd Q[dd][nq] K[dd][mk]
        float s[4][4] = {};
        #pragma unroll 16
        for (int dd = 0; dd < 64; dd++) {
            float4 av = *(float4*)&Qs[dd * 64 + ty * 4];
            float4 cv = *(float4*)&Ks[dd * 64 + tx * 4];
            float a[4] = {av.x, av.y, av.z, av.w};
            float c[4] = {cv.x, cv.y, cv.z, cv.w};
            #pragma unroll
            for (int i = 0; i < 4; i++)
                #pragma unroll
                for (int j = 0; j < 4; j++)
                    s[i][j] = fmaf(a[i], c[j], s[i][j]);
        }
        #pragma unroll
        for (int i = 0; i < 4; i++)
            #pragma unroll
            for (int j = 0; j < 4; j++)
                Ss[(ty * 4 + i) * 65 + tx * 4 + j] = s[i][j] * 0.125f;
        __syncthreads();

        // Online softmax per query row (64 rows -> threads 0..63)
        if (tid < 64) {
            float* row = &Ss[tid * 65];
            float mo = rowmax[tid], mn = mo;
            #pragma unroll 16
            for (int j = 0; j < 64; j++) mn = fmaxf(mn, row[j]);
            float cr = __expf(mo - mn);
            float sum = 0.f;
            #pragma unroll 16
            for (int j = 0; j < 64; j++) {
                float e = __expf(row[j] - mn);
                row[j] = e;
                sum += e;
            }
            rowsum[tid] = rowsum[tid] * cr + sum;
            rowmax[tid] = mn;
            corrs[tid]  = cr;
        }
        __syncthreads();

        // Rescale running O, then accumulate P @ V^T
        #pragma unroll
        for (int i = 0; i < 4; i++) {
            float cr = corrs[ty * 4 + i];
            #pragma unroll
            for (int j = 0; j < 4; j++) o[i][j] *= cr;
        }
        #pragma unroll 16
        for (int m = 0; m < 64; m++) {
            float4 vv = *(float4*)&Vst[m * 68 + tx * 4];
            float v[4] = {vv.x, vv.y, vv.z, vv.w};
            float p[4];
            #pragma unroll
            for (int i = 0; i < 4; i++) p[i] = Ss[(ty * 4 + i) * 65 + m];
            #pragma unroll
            for (int i = 0; i < 4; i++)
                #pragma unroll
                for (int j = 0; j < 4; j++)
                    o[i][j] = fmaf(p[i], v[j], o[i][j]);
        }
    }

    // Epilogue: normalize and write ao[b][h*64+dd][n0+nq]
    float inv[4];
    #pragma unroll
    for (int i = 0; i < 4; i++) inv[i] = 1.f / rowsum[ty * 4 + i];
    float* aob = ao + ((size_t)b * C_ + hh * HD) * NSP;
    #pragma unroll
    for (int j = 0; j < 4; j++) {
        int dd = tx * 4 + j;
        float4 ov = {o[0][j] * inv[0], o[1][j] * inv[1], o[2][j] * inv[2], o[3][j] * inv[3]};
        *(float4*)&aob[(size_t)dd * NSP + n0 + ty * 4] = ov;
    }
}

// ---------------------------------------------------------------------------
extern "C" void kernel_launch(void* const* d_in, const int* in_sizes, int n_in,
                              void* d_out, int out_size) {
    const float* x      = (const float*)d_in[0];
    const float* gamma  = (const float*)d_in[1];
    const float* beta   = (const float*)d_in[2];
    const float* w_qkv  = (const float*)d_in[3];
    const float* b_qkv  = (const float*)d_in[4];
    const float* w_proj = (const float*)d_in[5];
    const float* b_proj = (const float*)d_in[6];
    float* out = (float*)d_out;

    float *ph, *pq, *pa;
    cudaGetSymbolAddress((void**)&ph, g_h);
    cudaGetSymbolAddress((void**)&pq, g_qkv);
    cudaGetSymbolAddress((void**)&pa, g_ao);

    cudaFuncSetAttribute(attn_kernel, cudaFuncAttributeMaxDynamicSharedMemorySize, ATTN_SMEM);

    // 1) GroupNorm
    gn_kernel<<<B_ * NG, 256>>>(x, gamma, beta, ph);
    // 2) QKV projection: M = 1536
    gemm_kernel<<<dim3(NSP / 64, (3 * C_) / 64, B_), 256>>>(w_qkv, ph, b_qkv, nullptr, pq, 3 * C_);
    // 3) Fused attention
    attn_kernel<<<dim3(NSP / 64, NH, B_), 256, ATTN_SMEM>>>(pq, pa);
    // 4) Output projection + bias + residual: M = 512
    gemm_kernel<<<dim3(NSP / 64, C_ / 64, B_), 256>>>(w_proj, pa, b_proj, x, out, C_);
}

// round 2
// speedup vs baseline: 3.1566x; 3.1566x over previous
#include <cuda_runtime.h>
#include <math.h>
#include <stdint.h>

#define B_   16
#define C_   512
#define NSP  1024     // H*W
#define NG   32
#define GC   16
#define NH   8
#define HD   64

// Scratch (device globals; no allocations anywhere)
__device__ float g_h  [(size_t)B_ * C_ * NSP];
__device__ float g_qkv[(size_t)B_ * 3 * C_ * NSP];
__device__ float g_ao [(size_t)B_ * C_ * NSP];

__device__ __forceinline__ float to_tf32(float x) {
    uint32_t u;
    asm("cvt.rna.tf32.f32 %0, %1;" : "=r"(u) : "f"(x));
    return __uint_as_float(u);
}
__device__ __forceinline__ float ex2(float x) {
    float y;
    asm("ex2.approx.ftz.f32 %0, %1;" : "=f"(y) : "f"(x));
    return y;
}
__device__ __forceinline__ void mma8(float (&d)[4], const float (&a)[4], const float (&b)[2]) {
    asm volatile("mma.sync.aligned.m16n8k8.row.col.f32.tf32.tf32.f32 "
                 "{%0,%1,%2,%3}, {%4,%5,%6,%7}, {%8,%9}, {%0,%1,%2,%3};\n"
                 : "+f"(d[0]), "+f"(d[1]), "+f"(d[2]), "+f"(d[3])
                 : "r"(__float_as_uint(a[0])), "r"(__float_as_uint(a[1])),
                   "r"(__float_as_uint(a[2])), "r"(__float_as_uint(a[3])),
                   "r"(__float_as_uint(b[0])), "r"(__float_as_uint(b[1])));
}

// ---------------------------------------------------------------------------
// GroupNorm: one block per (batch, group).
// ---------------------------------------------------------------------------
__global__ __launch_bounds__(256) void gn_kernel(const float* __restrict__ x,
                                                 const float* __restrict__ gamma,
                                                 const float* __restrict__ beta,
                                                 float* __restrict__ hout) {
    int b = blockIdx.x >> 5;
    int g = blockIdx.x & 31;
    const float4* xp = (const float4*)(x    + ((size_t)b * C_ + g * GC) * NSP);
    float4*       hp = (float4*)      (hout + ((size_t)b * C_ + g * GC) * NSP);
    int tid = threadIdx.x;

    float s = 0.f, ss = 0.f;
    for (int i = tid; i < (GC * NSP) / 4; i += 256) {
        float4 v = xp[i];
        s  += v.x + v.y + v.z + v.w;
        ss += v.x * v.x + v.y * v.y + v.z * v.z + v.w * v.w;
    }
    __shared__ float rs[256], rss[256];
    rs[tid] = s; rss[tid] = ss;
    __syncthreads();
    for (int off = 128; off > 0; off >>= 1) {
        if (tid < off) { rs[tid] += rs[tid + off]; rss[tid] += rss[tid + off]; }
        __syncthreads();
    }
    const float invn = 1.f / (GC * NSP);
    float mean = rs[0] * invn;
    float var  = rss[0] * invn - mean * mean;
    float inv  = rsqrtf(var + 1e-5f);

    for (int i = tid; i < (GC * NSP) / 4; i += 256) {
        int cl = i >> 8;
        float ga = gamma[g * GC + cl] * inv;
        float be = beta [g * GC + cl];
        float4 v = xp[i];
        float4 o;
        o.x = (v.x - mean) * ga + be;
        o.y = (v.y - mean) * ga + be;
        o.z = (v.z - mean) * ga + be;
        o.w = (v.w - mean) * ga + be;
        hp[i] = o;
    }
}

// ---------------------------------------------------------------------------
// tf32 tensor-core batched GEMM: Out[b][m][n] = sum_c W[m][c]*H[b][c][n]+bias (+X)
// Block tile 128x128, K-chunk 16. 8 warps, warp tile 32x64.
// M = gridDim.y * 128.
// ---------------------------------------------------------------------------
__global__ __launch_bounds__(256) void gemm_tf32(const float* __restrict__ W,
                                                 const float* __restrict__ Hin,
                                                 const float* __restrict__ bias,
                                                 const float* __restrict__ X,
                                                 float* __restrict__ Out) {
    __shared__ float As[128][20];   // [m][k]  ld 20 (mod32=20: 8rx4c conflict-free)
    __shared__ float Bs[16][136];   // [k][n]  ld 136 (mod32=8: 4rx8c conflict-free)

    const int M = gridDim.y * 128;
    const float* Hb = Hin + (size_t)blockIdx.z * C_ * NSP;
    int m0 = blockIdx.y * 128, n0 = blockIdx.x * 128;
    int tid = threadIdx.x;
    int w = tid >> 5, lane = tid & 31;
    int r = lane >> 2, c = lane & 3;
    int wm = (w & 3) * 32, wn = (w >> 2) * 64;

    float acc[2][8][4];
    #pragma unroll
    for (int i = 0; i < 2; i++)
        #pragma unroll
        for (int j = 0; j < 8; j++)
            #pragma unroll
            for (int k = 0; k < 4; k++) acc[i][j][k] = 0.f;

    int am = tid >> 2, ak = (tid & 3) * 4;   // A loader: rows am, am+64
    int bk = tid >> 5, bn = (tid & 31) * 4;  // B loader: rows bk, bk+8

    float4 wa0, wa1, hb0, hb1;
    wa0 = *(const float4*)&W[(size_t)(m0 + am)      * C_ + ak];
    wa1 = *(const float4*)&W[(size_t)(m0 + am + 64) * C_ + ak];
    hb0 = *(const float4*)&Hb[(size_t)(bk)     * NSP + n0 + bn];
    hb1 = *(const float4*)&Hb[(size_t)(bk + 8) * NSP + n0 + bn];

    for (int ch = 0; ch < 32; ch++) {
        __syncthreads();
        As[am][ak + 0] = to_tf32(wa0.x); As[am][ak + 1] = to_tf32(wa0.y);
        As[am][ak + 2] = to_tf32(wa0.z); As[am][ak + 3] = to_tf32(wa0.w);
        As[am + 64][ak + 0] = to_tf32(wa1.x); As[am + 64][ak + 1] = to_tf32(wa1.y);
        As[am + 64][ak + 2] = to_tf32(wa1.z); As[am + 64][ak + 3] = to_tf32(wa1.w);
        Bs[bk][bn + 0] = to_tf32(hb0.x); Bs[bk][bn + 1] = to_tf32(hb0.y);
        Bs[bk][bn + 2] = to_tf32(hb0.z); Bs[bk][bn + 3] = to_tf32(hb0.w);
        Bs[bk + 8][bn + 0] = to_tf32(hb1.x); Bs[bk + 8][bn + 1] = to_tf32(hb1.y);
        Bs[bk + 8][bn + 2] = to_tf32(hb1.z); Bs[bk + 8][bn + 3] = to_tf32(hb1.w);
        __syncthreads();
        if (ch < 31) {
            int ch0 = (ch + 1) * 16;
            wa0 = *(const float4*)&W[(size_t)(m0 + am)      * C_ + ch0 + ak];
            wa1 = *(const float4*)&W[(size_t)(m0 + am + 64) * C_ + ch0 + ak];
            hb0 = *(const float4*)&Hb[(size_t)(ch0 + bk)     * NSP + n0 + bn];
            hb1 = *(const float4*)&Hb[(size_t)(ch0 + bk + 8) * NSP + n0 + bn];
        }
        #pragma unroll
        for (int ks = 0; ks < 16; ks += 8) {
            float a[2][4];
            #pragma unroll
            for (int i = 0; i < 2; i++) {
                a[i][0] = As[wm + i * 16 + r][ks + c];
                a[i][1] = As[wm + i * 16 + r + 8][ks + c];
                a[i][2] = As[wm + i * 16 + r][ks + c + 4];
                a[i][3] = As[wm + i * 16 + r + 8][ks + c + 4];
            }
            #pragma unroll
            for (int j = 0; j < 8; j++) {
                float b[2];
                b[0] = Bs[ks + c][wn + j * 8 + r];
                b[1] = Bs[ks + c + 4][wn + j * 8 + r];
                mma8(acc[0][j], a[0], b);
                mma8(acc[1][j], a[1], b);
            }
        }
    }

    const float* Xb = X ? (X + (size_t)blockIdx.z * M * NSP) : nullptr;
    float*       Ob = Out + (size_t)blockIdx.z * M * NSP;
    #pragma unroll
    for (int i = 0; i < 2; i++) {
        int mrow = m0 + wm + i * 16 + r;
        float bv0 = bias[mrow], bv1 = bias[mrow + 8];
        #pragma unroll
        for (int j = 0; j < 8; j++) {
            int col = n0 + wn + j * 8 + 2 * c;
            size_t i0 = (size_t)mrow * NSP + col;
            size_t i1 = (size_t)(mrow + 8) * NSP + col;
            float2 v0 = {acc[i][j][0] + bv0, acc[i][j][1] + bv0};
            float2 v1 = {acc[i][j][2] + bv1, acc[i][j][3] + bv1};
            if (Xb) {
                float2 x0 = *(const float2*)&Xb[i0];
                float2 x1 = *(const float2*)&Xb[i1];
                v0.x += x0.x; v0.y += x0.y;
                v1.x += x1.x; v1.y += x1.y;
            }
            *(float2*)&Ob[i0] = v0;
            *(float2*)&Ob[i1] = v1;
        }
    }
}

// ---------------------------------------------------------------------------
// Flash attention with tf32 mma. Block = (128 queries, head, batch).
// Warp w owns S/P/O rows 16w..16w+15 -> softmax needs only quad shuffles.
// ---------------------------------------------------------------------------
#define ATTN_SMEM_BYTES ((8704 + 8704 + 8960 + 17920) * 4)   // 177152

__global__ __launch_bounds__(256) void attn_tf32(const float* __restrict__ qkv,
                                                 float* __restrict__ ao) {
    extern __shared__ float sm[];
    float* Qs = sm;           // [64][136]  (d, nq)
    float* Ks = sm + 8704;    // [64][136]  (d, mk)
    float* Vs = sm + 17408;   // [64][140]  (d, mk)
    float* Ps = sm + 26368;   // [128][140] (nq, mk) per-warp private rows

    int qt = blockIdx.x, hh = blockIdx.y, b = blockIdx.z;
    const float* qb = qkv + ((size_t)b * (3 * C_) + hh * HD) * NSP;
    const float* kb = qb + (size_t)C_ * NSP;
    const float* vb = qb + (size_t)2 * C_ * NSP;
    int n0 = qt * 128;
    int tid = threadIdx.x, w = tid >> 5, lane = tid & 31;
    int r = lane >> 2, c = lane & 3;
    int prow = w * 16;

    // Load + convert Q tile [64][128]
    #pragma unroll
    for (int i = 0; i < 8; i++) {
        int f = tid + i * 256;
        int d = f >> 5, q = (f & 31) * 4;
        float4 v = *(const float4*)&qb[(size_t)d * NSP + n0 + q];
        v.x = to_tf32(v.x); v.y = to_tf32(v.y); v.z = to_tf32(v.z); v.w = to_tf32(v.w);
        *(float4*)&Qs[d * 136 + q] = v;
    }

    float o[8][4];
    #pragma unroll
    for (int j = 0; j < 8; j++)
        #pragma unroll
        for (int k = 0; k < 4; k++) o[j][k] = 0.f;
    float m0r = -1e30f, m1r = -1e30f, l0 = 0.f, l1 = 0.f;
    const float csc = 0.125f * 1.4426950408889634f;   // scale * log2(e)

    for (int kt = 0; kt < 8; kt++) {
        int mk0 = kt * 128;
        __syncthreads();
        #pragma unroll
        for (int i = 0; i < 8; i++) {
            int f = tid + i * 256;
            int d = f >> 5, q = (f & 31) * 4;
            float4 kv = *(const float4*)&kb[(size_t)d * NSP + mk0 + q];
            kv.x = to_tf32(kv.x); kv.y = to_tf32(kv.y); kv.z = to_tf32(kv.z); kv.w = to_tf32(kv.w);
            *(float4*)&Ks[d * 136 + q] = kv;
            float4 vv = *(const float4*)&vb[(size_t)d * NSP + mk0 + q];
            vv.x = to_tf32(vv.x); vv.y = to_tf32(vv.y); vv.z = to_tf32(vv.z); vv.w = to_tf32(vv.w);
            *(float4*)&Vs[d * 140 + q] = vv;
        }
        __syncthreads();

        // S = Q^T K  (warp rows prow..prow+15, all 128 key cols)
        float s[16][4];
        #pragma unroll
        for (int j = 0; j < 16; j++)
            #pragma unroll
            for (int k = 0; k < 4; k++) s[j][k] = 0.f;
        #pragma unroll
        for (int ks = 0; ks < 64; ks += 8) {
            float a[4];
            a[0] = Qs[(ks + c) * 136 + prow + r];
            a[1] = Qs[(ks + c) * 136 + prow + r + 8];
            a[2] = Qs[(ks + c + 4) * 136 + prow + r];
            a[3] = Qs[(ks + c + 4) * 136 + prow + r + 8];
            #pragma unroll
            for (int j = 0; j < 16; j++) {
                float bfr[2];
                bfr[0] = Ks[(ks + c) * 136 + j * 8 + r];
                bfr[1] = Ks[(ks + c + 4) * 136 + j * 8 + r];
                mma8(s[j], a, bfr);
            }
        }

        // Online softmax (rows prow+r, prow+r+8; quad lanes share rows)
        float tm0 = -1e30f, tm1 = -1e30f;
        #pragma unroll
        for (int j = 0; j < 16; j++) {
            tm0 = fmaxf(tm0, fmaxf(s[j][0], s[j][1]));
            tm1 = fmaxf(tm1, fmaxf(s[j][2], s[j][3]));
        }
        tm0 = fmaxf(tm0, __shfl_xor_sync(0xffffffffu, tm0, 1));
        tm0 = fmaxf(tm0, __shfl_xor_sync(0xffffffffu, tm0, 2));
        tm1 = fmaxf(tm1, __shfl_xor_sync(0xffffffffu, tm1, 1));
        tm1 = fmaxf(tm1, __shfl_xor_sync(0xffffffffu, tm1, 2));
        float nm0 = fmaxf(m0r, tm0), nm1 = fmaxf(m1r, tm1);
        float cr0 = ex2((m0r - nm0) * csc), cr1 = ex2((m1r - nm1) * csc);
        float sum0 = 0.f, sum1 = 0.f;
        #pragma unroll
        for (int j = 0; j < 16; j++) {
            s[j][0] = ex2((s[j][0] - nm0) * csc); sum0 += s[j][0];
            s[j][1] = ex2((s[j][1] - nm0) * csc); sum0 += s[j][1];
            s[j][2] = ex2((s[j][2] - nm1) * csc); sum1 += s[j][2];
            s[j][3] = ex2((s[j][3] - nm1) * csc); sum1 += s[j][3];
        }
        sum0 += __shfl_xor_sync(0xffffffffu, sum0, 1);
        sum0 += __shfl_xor_sync(0xffffffffu, sum0, 2);
        sum1 += __shfl_xor_sync(0xffffffffu, sum1, 1);
        sum1 += __shfl_xor_sync(0xffffffffu, sum1, 2);
        l0 = l0 * cr0 + sum0;
        l1 = l1 * cr1 + sum1;
        m0r = nm0; m1r = nm1;
        #pragma unroll
        for (int j = 0; j < 8; j++) {
            o[j][0] *= cr0; o[j][1] *= cr0;
            o[j][2] *= cr1; o[j][3] *= cr1;
        }

        // P -> per-warp smem rows (tf32), then PV mma
        #pragma unroll
        for (int j = 0; j < 16; j++) {
            float2 p0 = {to_tf32(s[j][0]), to_tf32(s[j][1])};
            float2 p1 = {to_tf32(s[j][2]), to_tf32(s[j][3])};
            *(float2*)&Ps[(prow + r) * 140 + j * 8 + 2 * c]     = p0;
            *(float2*)&Ps[(prow + r + 8) * 140 + j * 8 + 2 * c] = p1;
        }
        __syncwarp();
        #pragma unroll
        for (int kk = 0; kk < 16; kk++) {
            float a[4];
            a[0] = Ps[(prow + r) * 140 + kk * 8 + c];
            a[1] = Ps[(prow + r + 8) * 140 + kk * 8 + c];
            a[2] = Ps[(prow + r) * 140 + kk * 8 + c + 4];
            a[3] = Ps[(prow + r + 8) * 140 + kk * 8 + c + 4];
            #pragma unroll
            for (int j = 0; j < 8; j++) {
                float bfr[2];
                bfr[0] = Vs[(j * 8 + r) * 140 + kk * 8 + c];
                bfr[1] = Vs[(j * 8 + r) * 140 + kk * 8 + c + 4];
                mma8(o[j], a, bfr);
            }
        }
        __syncwarp();
    }

    // Epilogue: normalize, transpose via smem, coalesced store to ao[b][c][n]
    float il0 = 1.f / l0, il1 = 1.f / l1;
    __syncthreads();
    float* Osm = Ps;   // reuse as [64][136] (d, nq)
    #pragma unroll
    for (int j = 0; j < 8; j++) {
        int col = j * 8 + 2 * c;
        Osm[(col)     * 136 + prow + r]     = o[j][0] * il0;
        Osm[(col + 1) * 136 + prow + r]     = o[j][1] * il0;
        Osm[(col)     * 136 + prow + r + 8] = o[j][2] * il1;
        Osm[(col + 1) * 136 + prow + r + 8] = o[j][3] * il1;
    }
    __syncthreads();
    float* aob = ao + ((size_t)b * C_ + hh * HD) * NSP;
    #pragma unroll
    for (int i = 0; i < 8; i++) {
        int f = tid + i * 256;
        int d = f >> 5, q = (f & 31) * 4;
        *(float4*)&aob[(size_t)d * NSP + n0 + q] = *(float4*)&Osm[d * 136 + q];
    }
}

// ---------------------------------------------------------------------------
extern "C" void kernel_launch(void* const* d_in, const int* in_sizes, int n_in,
                              void* d_out, int out_size) {
    const float* x      = (const float*)d_in[0];
    const float* gamma  = (const float*)d_in[1];
    const float* beta   = (const float*)d_in[2];
    const float* w_qkv  = (const float*)d_in[3];
    const float* b_qkv  = (const float*)d_in[4];
    const float* w_proj = (const float*)d_in[5];
    const float* b_proj = (const float*)d_in[6];
    float* out = (float*)d_out;

    float *ph, *pq, *pa;
    cudaGetSymbolAddress((void**)&ph, g_h);
    cudaGetSymbolAddress((void**)&pq, g_qkv);
    cudaGetSymbolAddress((void**)&pa, g_ao);

    cudaFuncSetAttribute(attn_tf32, cudaFuncAttributeMaxDynamicSharedMemorySize, ATTN_SMEM_BYTES);

    gn_kernel<<<B_ * NG, 256>>>(x, gamma, beta, ph);
    gemm_tf32<<<dim3(8, 12, 16), 256>>>(w_qkv, ph, b_qkv, nullptr, pq);
    attn_tf32<<<dim3(8, NH, B_), 256, ATTN_SMEM_BYTES>>>(pq, pa);
    gemm_tf32<<<dim3(8, 4, 16), 256>>>(w_proj, pa, b_proj, x, out);
}

// round 3
// speedup vs baseline: 4.2370x; 1.3423x over previous
#include <cuda_runtime.h>
#include <cuda_fp16.h>
#include <math.h>
#include <stdint.h>

#define B_   16
#define C_   512
#define NSP  1024
#define NG   32
#define GC   16
#define NH   8
#define HD   64

__device__ float  g_h  [(size_t)B_ * C_ * NSP];
__device__ __half g_qkv[(size_t)B_ * 3 * C_ * NSP];
__device__ float  g_ao [(size_t)B_ * C_ * NSP];

__device__ __forceinline__ float to_tf32(float x) {
    uint32_t u;
    asm("cvt.rna.tf32.f32 %0, %1;" : "=r"(u) : "f"(x));
    return __uint_as_float(u);
}
__device__ __forceinline__ float ex2(float x) {
    float y;
    asm("ex2.approx.ftz.f32 %0, %1;" : "=f"(y) : "f"(x));
    return y;
}
__device__ __forceinline__ void mma8(float (&d)[4], const float (&a)[4], const float (&b)[2]) {
    asm volatile("mma.sync.aligned.m16n8k8.row.col.f32.tf32.tf32.f32 "
                 "{%0,%1,%2,%3}, {%4,%5,%6,%7}, {%8,%9}, {%0,%1,%2,%3};\n"
                 : "+f"(d[0]), "+f"(d[1]), "+f"(d[2]), "+f"(d[3])
                 : "r"(__float_as_uint(a[0])), "r"(__float_as_uint(a[1])),
                   "r"(__float_as_uint(a[2])), "r"(__float_as_uint(a[3])),
                   "r"(__float_as_uint(b[0])), "r"(__float_as_uint(b[1])));
}
__device__ __forceinline__ void mmaf16(float (&d)[4], const uint32_t* a, uint32_t b0, uint32_t b1) {
    asm volatile("mma.sync.aligned.m16n8k16.row.col.f32.f16.f16.f32 "
                 "{%0,%1,%2,%3}, {%4,%5,%6,%7}, {%8,%9}, {%0,%1,%2,%3};\n"
                 : "+f"(d[0]), "+f"(d[1]), "+f"(d[2]), "+f"(d[3])
                 : "r"(a[0]), "r"(a[1]), "r"(a[2]), "r"(a[3]), "r"(b0), "r"(b1));
}
__device__ __forceinline__ void ldsm4(uint32_t& r0, uint32_t& r1, uint32_t& r2, uint32_t& r3, uint32_t a) {
    asm volatile("ldmatrix.sync.aligned.m8n8.x4.shared.b16 {%0,%1,%2,%3}, [%4];\n"
                 : "=r"(r0), "=r"(r1), "=r"(r2), "=r"(r3) : "r"(a));
}
__device__ __forceinline__ void ldsm4t(uint32_t& r0, uint32_t& r1, uint32_t& r2, uint32_t& r3, uint32_t a) {
    asm volatile("ldmatrix.sync.aligned.m8n8.x4.trans.shared.b16 {%0,%1,%2,%3}, [%4];\n"
                 : "=r"(r0), "=r"(r1), "=r"(r2), "=r"(r3) : "r"(a));
}
__device__ __forceinline__ uint32_t packh2(float lo, float hi) {
    __half2 h = __floats2half2_rn(lo, hi);
    return *reinterpret_cast<uint32_t*>(&h);
}

// ---------------------------------------------------------------------------
// GroupNorm
// ---------------------------------------------------------------------------
__global__ __launch_bounds__(256) void gn_kernel(const float* __restrict__ x,
                                                 const float* __restrict__ gamma,
                                                 const float* __restrict__ beta,
                                                 float* __restrict__ hout) {
    int b = blockIdx.x >> 5;
    int g = blockIdx.x & 31;
    const float4* xp = (const float4*)(x    + ((size_t)b * C_ + g * GC) * NSP);
    float4*       hp = (float4*)      (hout + ((size_t)b * C_ + g * GC) * NSP);
    int tid = threadIdx.x;

    float s = 0.f, ss = 0.f;
    for (int i = tid; i < (GC * NSP) / 4; i += 256) {
        float4 v = xp[i];
        s  += v.x + v.y + v.z + v.w;
        ss += v.x * v.x + v.y * v.y + v.z * v.z + v.w * v.w;
    }
    __shared__ float rs[256], rss[256];
    rs[tid] = s; rss[tid] = ss;
    __syncthreads();
    for (int off = 128; off > 0; off >>= 1) {
        if (tid < off) { rs[tid] += rs[tid + off]; rss[tid] += rss[tid + off]; }
        __syncthreads();
    }
    const float invn = 1.f / (GC * NSP);
    float mean = rs[0] * invn;
    float var  = rss[0] * invn - mean * mean;
    float inv  = rsqrtf(var + 1e-5f);

    for (int i = tid; i < (GC * NSP) / 4; i += 256) {
        int cl = i >> 8;
        float ga = gamma[g * GC + cl] * inv;
        float be = beta [g * GC + cl];
        float4 v = xp[i];
        float4 o;
        o.x = (v.x - mean) * ga + be;
        o.y = (v.y - mean) * ga + be;
        o.z = (v.z - mean) * ga + be;
        o.w = (v.w - mean) * ga + be;
        hp[i] = o;
    }
}

// ---------------------------------------------------------------------------
// tf32 batched GEMM: Out = W @ H + bias (+X). Optional fp16 output (OutH).
// ---------------------------------------------------------------------------
__global__ __launch_bounds__(256) void gemm_tf32(const float* __restrict__ W,
                                                 const float* __restrict__ Hin,
                                                 const float* __restrict__ bias,
                                                 const float* __restrict__ X,
                                                 float* __restrict__ Out,
                                                 __half* __restrict__ OutH) {
    __shared__ float As[128][20];
    __shared__ float Bs[16][136];

    const int M = gridDim.y * 128;
    const float* Hb = Hin + (size_t)blockIdx.z * C_ * NSP;
    int m0 = blockIdx.y * 128, n0 = blockIdx.x * 128;
    int tid = threadIdx.x;
    int w = tid >> 5, lane = tid & 31;
    int r = lane >> 2, c = lane & 3;
    int wm = (w & 3) * 32, wn = (w >> 2) * 64;

    float acc[2][8][4];
    #pragma unroll
    for (int i = 0; i < 2; i++)
        #pragma unroll
        for (int j = 0; j < 8; j++)
            #pragma unroll
            for (int k = 0; k < 4; k++) acc[i][j][k] = 0.f;

    int am = tid >> 2, ak = (tid & 3) * 4;
    int bk = tid >> 5, bn = (tid & 31) * 4;

    float4 wa0, wa1, hb0, hb1;
    wa0 = *(const float4*)&W[(size_t)(m0 + am)      * C_ + ak];
    wa1 = *(const float4*)&W[(size_t)(m0 + am + 64) * C_ + ak];
    hb0 = *(const float4*)&Hb[(size_t)(bk)     * NSP + n0 + bn];
    hb1 = *(const float4*)&Hb[(size_t)(bk + 8) * NSP + n0 + bn];

    for (int ch = 0; ch < 32; ch++) {
        __syncthreads();
        As[am][ak + 0] = to_tf32(wa0.x); As[am][ak + 1] = to_tf32(wa0.y);
        As[am][ak + 2] = to_tf32(wa0.z); As[am][ak + 3] = to_tf32(wa0.w);
        As[am + 64][ak + 0] = to_tf32(wa1.x); As[am + 64][ak + 1] = to_tf32(wa1.y);
        As[am + 64][ak + 2] = to_tf32(wa1.z); As[am + 64][ak + 3] = to_tf32(wa1.w);
        Bs[bk][bn + 0] = to_tf32(hb0.x); Bs[bk][bn + 1] = to_tf32(hb0.y);
        Bs[bk][bn + 2] = to_tf32(hb0.z); Bs[bk][bn + 3] = to_tf32(hb0.w);
        Bs[bk + 8][bn + 0] = to_tf32(hb1.x); Bs[bk + 8][bn + 1] = to_tf32(hb1.y);
        Bs[bk + 8][bn + 2] = to_tf32(hb1.z); Bs[bk + 8][bn + 3] = to_tf32(hb1.w);
        __syncthreads();
        if (ch < 31) {
            int ch0 = (ch + 1) * 16;
            wa0 = *(const float4*)&W[(size_t)(m0 + am)      * C_ + ch0 + ak];
            wa1 = *(const float4*)&W[(size_t)(m0 + am + 64) * C_ + ch0 + ak];
            hb0 = *(const float4*)&Hb[(size_t)(ch0 + bk)     * NSP + n0 + bn];
            hb1 = *(const float4*)&Hb[(size_t)(ch0 + bk + 8) * NSP + n0 + bn];
        }
        #pragma unroll
        for (int ks = 0; ks < 16; ks += 8) {
            float a[2][4];
            #pragma unroll
            for (int i = 0; i < 2; i++) {
                a[i][0] = As[wm + i * 16 + r][ks + c];
                a[i][1] = As[wm + i * 16 + r + 8][ks + c];
                a[i][2] = As[wm + i * 16 + r][ks + c + 4];
                a[i][3] = As[wm + i * 16 + r + 8][ks + c + 4];
            }
            #pragma unroll
            for (int j = 0; j < 8; j++) {
                float b[2];
                b[0] = Bs[ks + c][wn + j * 8 + r];
                b[1] = Bs[ks + c + 4][wn + j * 8 + r];
                mma8(acc[0][j], a[0], b);
                mma8(acc[1][j], a[1], b);
            }
        }
    }

    #pragma unroll
    for (int i = 0; i < 2; i++) {
        int mrow = m0 + wm + i * 16 + r;
        float bv0 = bias[mrow], bv1 = bias[mrow + 8];
        #pragma unroll
        for (int j = 0; j < 8; j++) {
            int col = n0 + wn + j * 8 + 2 * c;
            size_t i0 = (size_t)mrow * NSP + col;
            size_t i1 = (size_t)(mrow + 8) * NSP + col;
            float2 v0 = {acc[i][j][0] + bv0, acc[i][j][1] + bv0};
            float2 v1 = {acc[i][j][2] + bv1, acc[i][j][3] + bv1};
            if (OutH) {
                __half* OHb = OutH + (size_t)blockIdx.z * M * NSP;
                *(__half2*)&OHb[i0] = __floats2half2_rn(v0.x, v0.y);
                *(__half2*)&OHb[i1] = __floats2half2_rn(v1.x, v1.y);
            } else {
                const float* Xb = X ? (X + (size_t)blockIdx.z * M * NSP) : nullptr;
                float*       Ob = Out + (size_t)blockIdx.z * M * NSP;
                if (Xb) {
                    float2 x0 = *(const float2*)&Xb[i0];
                    float2 x1 = *(const float2*)&Xb[i1];
                    v0.x += x0.x; v0.y += x0.y;
                    v1.x += x1.x; v1.y += x1.y;
                }
                *(float2*)&Ob[i0] = v0;
                *(float2*)&Ob[i1] = v1;
            }
        }
    }
}

// ---------------------------------------------------------------------------
// fp16 flash attention. Block = 128 queries x (head, batch). 8 warps.
// Warp owns 16 query rows. K-tiles of 64 keys. P kept in registers (FA2 trick).
// qkv is fp16 [b][3*512][1024]. Output fp32 [b][512][1024].
// smem: Qs half[64][136], Ks half[64][72], Vs half[64][72]; epilogue reuses as float.
// ---------------------------------------------------------------------------
#define ATTN_SMEM 35840

__global__ __launch_bounds__(256, 2) void attn_f16(const __half* __restrict__ qkv,
                                                   float* __restrict__ ao) {
    extern __shared__ char smc[];
    __half* Qs = (__half*)smc;              // [64][136]
    __half* Ks = (__half*)(smc + 17408);    // [64][72]
    __half* Vs = (__half*)(smc + 26624);    // [64][72]
    float*  Osm = (float*)smc;              // epilogue [64][136]

    int qt = blockIdx.x, hh = blockIdx.y, b = blockIdx.z;
    const __half* qb = qkv + ((size_t)b * (3 * C_) + hh * HD) * NSP;
    const __half* kb = qb + (size_t)C_ * NSP;
    const __half* vb = qb + (size_t)2 * C_ * NSP;
    int n0 = qt * 128;
    int tid = threadIdx.x, w = tid >> 5, l = tid & 31;
    int r = l >> 2, c = l & 3;
    int prow = w * 16;

    // Load Q tile: gmem [d][n] fp16 -> Qs[d][136]
    #pragma unroll
    for (int i = 0; i < 8; i++) {
        int f = tid + i * 256;
        int d = f >> 5, n4 = (f & 31) * 4;
        *(uint2*)&Qs[d * 136 + n4] = *(const uint2*)&qb[(size_t)d * NSP + n0 + n4];
    }

    // ldmatrix lane base addresses (byte)
    uint32_t qs0 = (uint32_t)__cvta_generic_to_shared(Qs);
    uint32_t ks0 = (uint32_t)__cvta_generic_to_shared(Ks);
    uint32_t vs0 = (uint32_t)__cvta_generic_to_shared(Vs);
    // A (Q^T): row = (l&7) + (l>>4)*8, col = prow + ((l>>3)&1)*8
    uint32_t qa = qs0 + (((l & 7) + (l >> 4) * 8) * 136 + prow + ((l >> 3) & 1) * 8) * 2;
    // B (K): row = (l&7) + ((l>>3)&1)*8, col = (l>>4)*8
    uint32_t ka = ks0 + (((l & 7) + ((l >> 3) & 1) * 8) * 72 + (l >> 4) * 8) * 2;
    // B (V, non-trans): row = (l&7) + (l>>4)*8, col = ((l>>3)&1)*8
    uint32_t va = vs0 + (((l & 7) + (l >> 4) * 8) * 72 + ((l >> 3) & 1) * 8) * 2;

    float o[8][4];
    #pragma unroll
    for (int j = 0; j < 8; j++)
        #pragma unroll
        for (int k = 0; k < 4; k++) o[j][k] = 0.f;
    float mr0 = -1e30f, mr1 = -1e30f, l0 = 0.f, l1 = 0.f;
    const float csc = 0.125f * 1.4426950408889634f;

    for (int kt = 0; kt < 16; kt++) {
        int mk0 = kt * 64;
        __syncthreads();
        #pragma unroll
        for (int i = 0; i < 4; i++) {
            int f = tid + i * 256;
            int d = f >> 4, m4 = (f & 15) * 4;
            *(uint2*)&Ks[d * 72 + m4] = *(const uint2*)&kb[(size_t)d * NSP + mk0 + m4];
            *(uint2*)&Vs[d * 72 + m4] = *(const uint2*)&vb[(size_t)d * NSP + mk0 + m4];
        }
        __syncthreads();

        // S = Q^T K : 16 rows x 64 keys per warp
        float s[8][4];
        #pragma unroll
        for (int j = 0; j < 8; j++)
            #pragma unroll
            for (int k = 0; k < 4; k++) s[j][k] = 0.f;
        #pragma unroll
        for (int dk = 0; dk < 4; dk++) {
            uint32_t a[4];
            ldsm4t(a[0], a[1], a[2], a[3], qa + dk * 16 * 272);
            #pragma unroll
            for (int jj = 0; jj < 4; jj++) {
                uint32_t bq[4];
                ldsm4t(bq[0], bq[1], bq[2], bq[3], ka + dk * 16 * 144 + jj * 32);
                mmaf16(s[2 * jj], a, bq[0], bq[1]);
                mmaf16(s[2 * jj + 1], a, bq[2], bq[3]);
            }
        }

        // Online softmax (rows r, r+8; quad lanes hold different cols)
        float tm0 = -1e30f, tm1 = -1e30f;
        #pragma unroll
        for (int j = 0; j < 8; j++) {
            tm0 = fmaxf(tm0, fmaxf(s[j][0], s[j][1]));
            tm1 = fmaxf(tm1, fmaxf(s[j][2], s[j][3]));
        }
        tm0 = fmaxf(tm0, __shfl_xor_sync(0xffffffffu, tm0, 1));
        tm0 = fmaxf(tm0, __shfl_xor_sync(0xffffffffu, tm0, 2));
        tm1 = fmaxf(tm1, __shfl_xor_sync(0xffffffffu, tm1, 1));
        tm1 = fmaxf(tm1, __shfl_xor_sync(0xffffffffu, tm1, 2));
        float nm0 = fmaxf(mr0, tm0), nm1 = fmaxf(mr1, tm1);
        float cr0 = ex2((mr0 - nm0) * csc), cr1 = ex2((mr1 - nm1) * csc);
        float sum0 = 0.f, sum1 = 0.f;
        #pragma unroll
        for (int j = 0; j < 8; j++) {
            s[j][0] = ex2((s[j][0] - nm0) * csc); sum0 += s[j][0];
            s[j][1] = ex2((s[j][1] - nm0) * csc); sum0 += s[j][1];
            s[j][2] = ex2((s[j][2] - nm1) * csc); sum1 += s[j][2];
            s[j][3] = ex2((s[j][3] - nm1) * csc); sum1 += s[j][3];
        }
        sum0 += __shfl_xor_sync(0xffffffffu, sum0, 1);
        sum0 += __shfl_xor_sync(0xffffffffu, sum0, 2);
        sum1 += __shfl_xor_sync(0xffffffffu, sum1, 1);
        sum1 += __shfl_xor_sync(0xffffffffu, sum1, 2);
        l0 = l0 * cr0 + sum0;
        l1 = l1 * cr1 + sum1;
        mr0 = nm0; mr1 = nm1;
        #pragma unroll
        for (int j = 0; j < 8; j++) {
            o[j][0] *= cr0; o[j][1] *= cr0;
            o[j][2] *= cr1; o[j][3] *= cr1;
        }

        // Pack P -> fp16 A-fragments (register only)
        uint32_t ph[16];
        #pragma unroll
        for (int q = 0; q < 8; q++) {
            ph[2 * q]     = packh2(s[q][0], s[q][1]);
            ph[2 * q + 1] = packh2(s[q][2], s[q][3]);
        }

        // O += P @ V^T
        #pragma unroll
        for (int kk = 0; kk < 4; kk++) {
            #pragma unroll
            for (int dd = 0; dd < 4; dd++) {
                uint32_t bv[4];
                ldsm4(bv[0], bv[1], bv[2], bv[3], va + dd * 16 * 144 + kk * 32);
                mmaf16(o[2 * dd],     &ph[4 * kk], bv[0], bv[1]);
                mmaf16(o[2 * dd + 1], &ph[4 * kk], bv[2], bv[3]);
            }
        }
    }

    // Epilogue: normalize, transpose via smem, coalesced fp32 store
    float il0 = 1.f / l0, il1 = 1.f / l1;
    __syncthreads();
    #pragma unroll
    for (int j = 0; j < 8; j++) {
        int d = 8 * j + 2 * c;
        Osm[(d)     * 136 + prow + r]     = o[j][0] * il0;
        Osm[(d + 1) * 136 + prow + r]     = o[j][1] * il0;
        Osm[(d)     * 136 + prow + r + 8] = o[j][2] * il1;
        Osm[(d + 1) * 136 + prow + r + 8] = o[j][3] * il1;
    }
    __syncthreads();
    float* aob = ao + ((size_t)b * C_ + hh * HD) * NSP;
    #pragma unroll
    for (int i = 0; i < 8; i++) {
        int f = tid + i * 256;
        int d = f >> 5, n4 = (f & 31) * 4;
        *(float4*)&aob[(size_t)d * NSP + n0 + n4] = *(float4*)&Osm[d * 136 + n4];
    }
}

// ---------------------------------------------------------------------------
extern "C" void kernel_launch(void* const* d_in, const int* in_sizes, int n_in,
                              void* d_out, int out_size) {
    const float* x      = (const float*)d_in[0];
    const float* gamma  = (const float*)d_in[1];
    const float* beta   = (const float*)d_in[2];
    const float* w_qkv  = (const float*)d_in[3];
    const float* b_qkv  = (const float*)d_in[4];
    const float* w_proj = (const float*)d_in[5];
    const float* b_proj = (const float*)d_in[6];
    float* out = (float*)d_out;

    float *ph, *pa;
    __half* pq;
    cudaGetSymbolAddress((void**)&ph, g_h);
    cudaGetSymbolAddress((void**)&pq, g_qkv);
    cudaGetSymbolAddress((void**)&pa, g_ao);

    gn_kernel<<<B_ * NG, 256>>>(x, gamma, beta, ph);
    gemm_tf32<<<dim3(8, 12, 16), 256>>>(w_qkv, ph, b_qkv, nullptr, nullptr, pq);
    attn_f16<<<dim3(8, NH, B_), 256, ATTN_SMEM>>>(pq, pa);
    gemm_tf32<<<dim3(8, 4, 16), 256>>>(w_proj, pa, b_proj, x, out, nullptr);
}

// round 4
// speedup vs baseline: 4.4779x; 1.0569x over previous
#include <cuda_runtime.h>
#include <cuda_fp16.h>
#include <math.h>
#include <stdint.h>

#define B_   16
#define C_   512
#define NSP  1024
#define NG   32
#define GC   16
#define NH   8
#define HD   64

__device__ float  g_h  [(size_t)B_ * C_ * NSP];
__device__ __half g_qkv[(size_t)B_ * 3 * C_ * NSP];
__device__ float  g_ao [(size_t)B_ * C_ * NSP];

__device__ __forceinline__ float to_tf32(float x) {
    uint32_t u;
    asm("cvt.rna.tf32.f32 %0, %1;" : "=r"(u) : "f"(x));
    return __uint_as_float(u);
}
__device__ __forceinline__ float ex2(float x) {
    float y;
    asm("ex2.approx.ftz.f32 %0, %1;" : "=f"(y) : "f"(x));
    return y;
}
__device__ __forceinline__ uint32_t h2ex2(uint32_t x) {
    uint32_t y;
    asm("ex2.approx.f16x2 %0, %1;" : "=r"(y) : "r"(x));
    return y;
}
__device__ __forceinline__ void mma8(float (&d)[4], const float (&a)[4], const float (&b)[2]) {
    asm volatile("mma.sync.aligned.m16n8k8.row.col.f32.tf32.tf32.f32 "
                 "{%0,%1,%2,%3}, {%4,%5,%6,%7}, {%8,%9}, {%0,%1,%2,%3};\n"
                 : "+f"(d[0]), "+f"(d[1]), "+f"(d[2]), "+f"(d[3])
                 : "r"(__float_as_uint(a[0])), "r"(__float_as_uint(a[1])),
                   "r"(__float_as_uint(a[2])), "r"(__float_as_uint(a[3])),
                   "r"(__float_as_uint(b[0])), "r"(__float_as_uint(b[1])));
}
__device__ __forceinline__ void mmaf16(float (&d)[4], const uint32_t* a, uint32_t b0, uint32_t b1) {
    asm volatile("mma.sync.aligned.m16n8k16.row.col.f32.f16.f16.f32 "
                 "{%0,%1,%2,%3}, {%4,%5,%6,%7}, {%8,%9}, {%0,%1,%2,%3};\n"
                 : "+f"(d[0]), "+f"(d[1]), "+f"(d[2]), "+f"(d[3])
                 : "r"(a[0]), "r"(a[1]), "r"(a[2]), "r"(a[3]), "r"(b0), "r"(b1));
}
__device__ __forceinline__ void ldsm4(uint32_t& r0, uint32_t& r1, uint32_t& r2, uint32_t& r3, uint32_t a) {
    asm volatile("ldmatrix.sync.aligned.m8n8.x4.shared.b16 {%0,%1,%2,%3}, [%4];\n"
                 : "=r"(r0), "=r"(r1), "=r"(r2), "=r"(r3) : "r"(a));
}
__device__ __forceinline__ void ldsm4t(uint32_t& r0, uint32_t& r1, uint32_t& r2, uint32_t& r3, uint32_t a) {
    asm volatile("ldmatrix.sync.aligned.m8n8.x4.trans.shared.b16 {%0,%1,%2,%3}, [%4];\n"
                 : "=r"(r0), "=r"(r1), "=r"(r2), "=r"(r3) : "r"(a));
}
__device__ __forceinline__ uint32_t packh2(float lo, float hi) {
    __half2 h = __floats2half2_rn(lo, hi);
    return *reinterpret_cast<uint32_t*>(&h);
}

// ---------------------------------------------------------------------------
// GroupNorm
// ---------------------------------------------------------------------------
__global__ __launch_bounds__(512) void gn_kernel(const float* __restrict__ x,
                                                 const float* __restrict__ gamma,
                                                 const float* __restrict__ beta,
                                                 float* __restrict__ hout) {
    int b = blockIdx.x >> 5;
    int g = blockIdx.x & 31;
    const float4* xp = (const float4*)(x    + ((size_t)b * C_ + g * GC) * NSP);
    float4*       hp = (float4*)      (hout + ((size_t)b * C_ + g * GC) * NSP);
    int tid = threadIdx.x;

    float s = 0.f, ss = 0.f;
    float4 v[8];
    #pragma unroll
    for (int i = 0; i < 8; i++) {
        v[i] = xp[tid + i * 512];
        s  += v[i].x + v[i].y + v[i].z + v[i].w;
        ss += v[i].x * v[i].x + v[i].y * v[i].y + v[i].z * v[i].z + v[i].w * v[i].w;
    }
    __shared__ float rs[512], rss[512];
    rs[tid] = s; rss[tid] = ss;
    __syncthreads();
    for (int off = 256; off > 0; off >>= 1) {
        if (tid < off) { rs[tid] += rs[tid + off]; rss[tid] += rss[tid + off]; }
        __syncthreads();
    }
    const float invn = 1.f / (GC * NSP);
    float mean = rs[0] * invn;
    float var  = rss[0] * invn - mean * mean;
    float inv  = rsqrtf(var + 1e-5f);

    #pragma unroll
    for (int i = 0; i < 8; i++) {
        int idx = tid + i * 512;
        int cl = idx >> 8;
        float ga = gamma[g * GC + cl] * inv;
        float be = beta [g * GC + cl];
        float4 o;
        o.x = (v[i].x - mean) * ga + be;
        o.y = (v[i].y - mean) * ga + be;
        o.z = (v[i].z - mean) * ga + be;
        o.w = (v[i].w - mean) * ga + be;
        hp[idx] = o;
    }
}

// ---------------------------------------------------------------------------
// tf32 batched GEMM: Out = W @ H + bias (+X). Optional fp16 output (OutH).
// ---------------------------------------------------------------------------
__global__ __launch_bounds__(256) void gemm_tf32(const float* __restrict__ W,
                                                 const float* __restrict__ Hin,
                                                 const float* __restrict__ bias,
                                                 const float* __restrict__ X,
                                                 float* __restrict__ Out,
                                                 __half* __restrict__ OutH) {
    __shared__ float As[128][20];
    __shared__ float Bs[16][136];

    const int M = gridDim.y * 128;
    const float* Hb = Hin + (size_t)blockIdx.z * C_ * NSP;
    int m0 = blockIdx.y * 128, n0 = blockIdx.x * 128;
    int tid = threadIdx.x;
    int w = tid >> 5, lane = tid & 31;
    int r = lane >> 2, c = lane & 3;
    int wm = (w & 3) * 32, wn = (w >> 2) * 64;

    float acc[2][8][4];
    #pragma unroll
    for (int i = 0; i < 2; i++)
        #pragma unroll
        for (int j = 0; j < 8; j++)
            #pragma unroll
            for (int k = 0; k < 4; k++) acc[i][j][k] = 0.f;

    int am = tid >> 2, ak = (tid & 3) * 4;
    int bk = tid >> 5, bn = (tid & 31) * 4;

    float4 wa0, wa1, hb0, hb1;
    wa0 = *(const float4*)&W[(size_t)(m0 + am)      * C_ + ak];
    wa1 = *(const float4*)&W[(size_t)(m0 + am + 64) * C_ + ak];
    hb0 = *(const float4*)&Hb[(size_t)(bk)     * NSP + n0 + bn];
    hb1 = *(const float4*)&Hb[(size_t)(bk + 8) * NSP + n0 + bn];

    for (int ch = 0; ch < 32; ch++) {
        __syncthreads();
        As[am][ak + 0] = to_tf32(wa0.x); As[am][ak + 1] = to_tf32(wa0.y);
        As[am][ak + 2] = to_tf32(wa0.z); As[am][ak + 3] = to_tf32(wa0.w);
        As[am + 64][ak + 0] = to_tf32(wa1.x); As[am + 64][ak + 1] = to_tf32(wa1.y);
        As[am + 64][ak + 2] = to_tf32(wa1.z); As[am + 64][ak + 3] = to_tf32(wa1.w);
        Bs[bk][bn + 0] = to_tf32(hb0.x); Bs[bk][bn + 1] = to_tf32(hb0.y);
        Bs[bk][bn + 2] = to_tf32(hb0.z); Bs[bk][bn + 3] = to_tf32(hb0.w);
        Bs[bk + 8][bn + 0] = to_tf32(hb1.x); Bs[bk + 8][bn + 1] = to_tf32(hb1.y);
        Bs[bk + 8][bn + 2] = to_tf32(hb1.z); Bs[bk + 8][bn + 3] = to_tf32(hb1.w);
        __syncthreads();
        if (ch < 31) {
            int ch0 = (ch + 1) * 16;
            wa0 = *(const float4*)&W[(size_t)(m0 + am)      * C_ + ch0 + ak];
            wa1 = *(const float4*)&W[(size_t)(m0 + am + 64) * C_ + ch0 + ak];
            hb0 = *(const float4*)&Hb[(size_t)(ch0 + bk)     * NSP + n0 + bn];
            hb1 = *(const float4*)&Hb[(size_t)(ch0 + bk + 8) * NSP + n0 + bn];
        }
        #pragma unroll
        for (int ks = 0; ks < 16; ks += 8) {
            float a[2][4];
            #pragma unroll
            for (int i = 0; i < 2; i++) {
                a[i][0] = As[wm + i * 16 + r][ks + c];
                a[i][1] = As[wm + i * 16 + r + 8][ks + c];
                a[i][2] = As[wm + i * 16 + r][ks + c + 4];
                a[i][3] = As[wm + i * 16 + r + 8][ks + c + 4];
            }
            #pragma unroll
            for (int j = 0; j < 8; j++) {
                float b[2];
                b[0] = Bs[ks + c][wn + j * 8 + r];
                b[1] = Bs[ks + c + 4][wn + j * 8 + r];
                mma8(acc[0][j], a[0], b);
                mma8(acc[1][j], a[1], b);
            }
        }
    }

    #pragma unroll
    for (int i = 0; i < 2; i++) {
        int mrow = m0 + wm + i * 16 + r;
        float bv0 = bias[mrow], bv1 = bias[mrow + 8];
        #pragma unroll
        for (int j = 0; j < 8; j++) {
            int col = n0 + wn + j * 8 + 2 * c;
            size_t i0 = (size_t)mrow * NSP + col;
            size_t i1 = (size_t)(mrow + 8) * NSP + col;
            float2 v0 = {acc[i][j][0] + bv0, acc[i][j][1] + bv0};
            float2 v1 = {acc[i][j][2] + bv1, acc[i][j][3] + bv1};
            if (OutH) {
                __half* OHb = OutH + (size_t)blockIdx.z * M * NSP;
                *(__half2*)&OHb[i0] = __floats2half2_rn(v0.x, v0.y);
                *(__half2*)&OHb[i1] = __floats2half2_rn(v1.x, v1.y);
            } else {
                const float* Xb = X ? (X + (size_t)blockIdx.z * M * NSP) : nullptr;
                float*       Ob = Out + (size_t)blockIdx.z * M * NSP;
                if (Xb) {
                    float2 x0 = *(const float2*)&Xb[i0];
                    float2 x1 = *(const float2*)&Xb[i1];
                    v0.x += x0.x; v0.y += x0.y;
                    v1.x += x1.x; v1.y += x1.y;
                }
                *(float2*)&Ob[i0] = v0;
                *(float2*)&Ob[i1] = v1;
            }
        }
    }
}

// ---------------------------------------------------------------------------
// fp16 flash attention. 128 queries x (head,batch) per block. 8 warps.
// exp via ex2.approx.f16x2 (one MUFU op = 2 P-halves, result IS the fragment).
// Row sums via ones-column MMA. K/V register-prefetch double buffering.
// ---------------------------------------------------------------------------
#define ATTN_SMEM 35840

__global__ __launch_bounds__(256, 2) void attn_f16(const __half* __restrict__ qkv,
                                                   float* __restrict__ ao) {
    extern __shared__ char smc[];
    __half* Qs = (__half*)smc;              // [64][136]
    __half* Ks = (__half*)(smc + 17408);    // [64][72]
    __half* Vs = (__half*)(smc + 26624);    // [64][72]
    float*  Osm = (float*)smc;              // epilogue [64][136]

    int qt = blockIdx.x, hh = blockIdx.y, b = blockIdx.z;
    const __half* qb = qkv + ((size_t)b * (3 * C_) + hh * HD) * NSP;
    const __half* kb = qb + (size_t)C_ * NSP;
    const __half* vb = qb + (size_t)2 * C_ * NSP;
    int n0 = qt * 128;
    int tid = threadIdx.x, w = tid >> 5, l = tid & 31;
    int r = l >> 2, c = l & 3;
    int prow = w * 16;

    // Load Q tile: gmem [d][n] fp16 -> Qs[d][136]
    #pragma unroll
    for (int i = 0; i < 8; i++) {
        int f = tid + i * 256;
        int d = f >> 5, n4 = (f & 31) * 4;
        *(uint2*)&Qs[d * 136 + n4] = *(const uint2*)&qb[(size_t)d * NSP + n0 + n4];
    }

    uint32_t qs0 = (uint32_t)__cvta_generic_to_shared(Qs);
    uint32_t ks0 = (uint32_t)__cvta_generic_to_shared(Ks);
    uint32_t vs0 = (uint32_t)__cvta_generic_to_shared(Vs);
    uint32_t qa = qs0 + (((l & 7) + (l >> 4) * 8) * 136 + prow + ((l >> 3) & 1) * 8) * 2;
    uint32_t ka = ks0 + (((l & 7) + ((l >> 3) & 1) * 8) * 72 + (l >> 4) * 8) * 2;
    uint32_t va = vs0 + (((l & 7) + (l >> 4) * 8) * 72 + ((l >> 3) & 1) * 8) * 2;

    // K/V loader indices + prefetch registers
    int ld_d = tid >> 4, ld_m4 = (tid & 15) * 4;
    uint2 kreg[4], vreg[4];
    #pragma unroll
    for (int i = 0; i < 4; i++) {
        int d = ld_d + i * 16;
        kreg[i] = *(const uint2*)&kb[(size_t)d * NSP + ld_m4];
        vreg[i] = *(const uint2*)&vb[(size_t)d * NSP + ld_m4];
    }

    float o[8][4];
    #pragma unroll
    for (int j = 0; j < 8; j++)
        #pragma unroll
        for (int k = 0; k < 4; k++) o[j][k] = 0.f;
    float osum[4] = {0.f, 0.f, 0.f, 0.f};
    float mr0 = -1e30f, mr1 = -1e30f;
    const float csc = 0.125f * 1.4426950408889634f;
    const uint32_t ONE2 = 0x3C003C00u;   // half2(1,1)

    for (int kt = 0; kt < 16; kt++) {
        __syncthreads();
        #pragma unroll
        for (int i = 0; i < 4; i++) {
            int d = ld_d + i * 16;
            *(uint2*)&Ks[d * 72 + ld_m4] = kreg[i];
            *(uint2*)&Vs[d * 72 + ld_m4] = vreg[i];
        }
        __syncthreads();
        if (kt < 15) {
            int mk1 = (kt + 1) * 64;
            #pragma unroll
            for (int i = 0; i < 4; i++) {
                int d = ld_d + i * 16;
                kreg[i] = *(const uint2*)&kb[(size_t)d * NSP + mk1 + ld_m4];
                vreg[i] = *(const uint2*)&vb[(size_t)d * NSP + mk1 + ld_m4];
            }
        }

        // S = Q^T K : 16 rows x 64 keys per warp
        float s[8][4];
        #pragma unroll
        for (int j = 0; j < 8; j++)
            #pragma unroll
            for (int k = 0; k < 4; k++) s[j][k] = 0.f;
        #pragma unroll
        for (int dk = 0; dk < 4; dk++) {
            uint32_t a[4];
            ldsm4t(a[0], a[1], a[2], a[3], qa + dk * 16 * 272);
            #pragma unroll
            for (int jj = 0; jj < 4; jj++) {
                uint32_t bq[4];
                ldsm4t(bq[0], bq[1], bq[2], bq[3], ka + dk * 16 * 144 + jj * 32);
                mmaf16(s[2 * jj], a, bq[0], bq[1]);
                mmaf16(s[2 * jj + 1], a, bq[2], bq[3]);
            }
        }

        // Online softmax: max reduce over quad lanes
        float tm0 = -1e30f, tm1 = -1e30f;
        #pragma unroll
        for (int j = 0; j < 8; j++) {
            tm0 = fmaxf(tm0, fmaxf(s[j][0], s[j][1]));
            tm1 = fmaxf(tm1, fmaxf(s[j][2], s[j][3]));
        }
        tm0 = fmaxf(tm0, __shfl_xor_sync(0xffffffffu, tm0, 1));
        tm0 = fmaxf(tm0, __shfl_xor_sync(0xffffffffu, tm0, 2));
        tm1 = fmaxf(tm1, __shfl_xor_sync(0xffffffffu, tm1, 1));
        tm1 = fmaxf(tm1, __shfl_xor_sync(0xffffffffu, tm1, 2));
        float nm0 = fmaxf(mr0, tm0), nm1 = fmaxf(mr1, tm1);
        float cr0 = ex2((mr0 - nm0) * csc), cr1 = ex2((mr1 - nm1) * csc);
        mr0 = nm0; mr1 = nm1;
        float b0 = nm0 * csc, b1 = nm1 * csc;

        // P = exp2(s*csc - b) in fp16x2 — directly forms A fragments
        uint32_t ph[16];
        #pragma unroll
        for (int q = 0; q < 8; q++) {
            ph[2 * q]     = h2ex2(packh2(fmaf(s[q][0], csc, -b0), fmaf(s[q][1], csc, -b0)));
            ph[2 * q + 1] = h2ex2(packh2(fmaf(s[q][2], csc, -b1), fmaf(s[q][3], csc, -b1)));
        }

        // Rescale running O and row-sum accumulators
        #pragma unroll
        for (int j = 0; j < 8; j++) {
            o[j][0] *= cr0; o[j][1] *= cr0;
            o[j][2] *= cr1; o[j][3] *= cr1;
        }
        osum[0] *= cr0; osum[1] *= cr0; osum[2] *= cr1; osum[3] *= cr1;

        // O += P @ V^T ; osum += P @ ones
        #pragma unroll
        for (int kk = 0; kk < 4; kk++) {
            mmaf16(osum, &ph[4 * kk], ONE2, ONE2);
            #pragma unroll
            for (int dd = 0; dd < 4; dd++) {
                uint32_t bv[4];
                ldsm4(bv[0], bv[1], bv[2], bv[3], va + dd * 16 * 144 + kk * 32);
                mmaf16(o[2 * dd],     &ph[4 * kk], bv[0], bv[1]);
                mmaf16(o[2 * dd + 1], &ph[4 * kk], bv[2], bv[3]);
            }
        }
    }

    // Epilogue: normalize (osum[0]=row r sum, osum[2]=row r+8 sum), transpose, store
    float il0 = 1.f / osum[0], il1 = 1.f / osum[2];
    __syncthreads();
    #pragma unroll
    for (int j = 0; j < 8; j++) {
        int d = 8 * j + 2 * c;
        Osm[(d)     * 136 + prow + r]     = o[j][0] * il0;
        Osm[(d + 1) * 136 + prow + r]     = o[j][1] * il0;
        Osm[(d)     * 136 + prow + r + 8] = o[j][2] * il1;
        Osm[(d + 1) * 136 + prow + r + 8] = o[j][3] * il1;
    }
    __syncthreads();
    float* aob = ao + ((size_t)b * C_ + hh * HD) * NSP;
    #pragma unroll
    for (int i = 0; i < 8; i++) {
        int f = tid + i * 256;
        int d = f >> 5, n4 = (f & 31) * 4;
        *(float4*)&aob[(size_t)d * NSP + n0 + n4] = *(float4*)&Osm[d * 136 + n4];
    }
}

// ---------------------------------------------------------------------------
extern "C" void kernel_launch(void* const* d_in, const int* in_sizes, int n_in,
                              void* d_out, int out_size) {
    const float* x      = (const float*)d_in[0];
    const float* gamma  = (const float*)d_in[1];
    const float* beta   = (const float*)d_in[2];
    const float* w_qkv  = (const float*)d_in[3];
    const float* b_qkv  = (const float*)d_in[4];
    const float* w_proj = (const float*)d_in[5];
    const float* b_proj = (const float*)d_in[6];
    float* out = (float*)d_out;

    float *ph, *pa;
    __half* pq;
    cudaGetSymbolAddress((void**)&ph, g_h);
    cudaGetSymbolAddress((void**)&pq, g_qkv);
    cudaGetSymbolAddress((void**)&pa, g_ao);

    gn_kernel<<<B_ * NG, 512>>>(x, gamma, beta, ph);
    gemm_tf32<<<dim3(8, 12, 16), 256>>>(w_qkv, ph, b_qkv, nullptr, nullptr, pq);
    attn_f16<<<dim3(8, NH, B_), 256, ATTN_SMEM>>>(pq, pa);
    gemm_tf32<<<dim3(8, 4, 16), 256>>>(w_proj, pa, b_proj, x, out, nullptr);
}

// round 5
// speedup vs baseline: 5.1428x; 1.1485x over previous
#include <cuda_runtime.h>
#include <cuda_fp16.h>
#include <math.h>
#include <stdint.h>

#define B_   16
#define C_   512
#define NSP  1024
#define NG   32
#define GC   16
#define NH   8
#define HD   64

__device__ float  g_h  [(size_t)B_ * C_ * NSP];
__device__ __half g_qkv[(size_t)B_ * 3 * C_ * NSP];
__device__ float  g_ao [(size_t)B_ * C_ * NSP];

__device__ __forceinline__ float ex2(float x) {
    float y;
    asm("ex2.approx.ftz.f32 %0, %1;" : "=f"(y) : "f"(x));
    return y;
}
__device__ __forceinline__ uint32_t h2ex2(uint32_t x) {
    uint32_t y;
    asm("ex2.approx.f16x2 %0, %1;" : "=r"(y) : "r"(x));
    return y;
}
__device__ __forceinline__ void mma8(float (&d)[4], const float (&a)[4], const float (&b)[2]) {
    asm volatile("mma.sync.aligned.m16n8k8.row.col.f32.tf32.tf32.f32 "
                 "{%0,%1,%2,%3}, {%4,%5,%6,%7}, {%8,%9}, {%0,%1,%2,%3};\n"
                 : "+f"(d[0]), "+f"(d[1]), "+f"(d[2]), "+f"(d[3])
                 : "r"(__float_as_uint(a[0])), "r"(__float_as_uint(a[1])),
                   "r"(__float_as_uint(a[2])), "r"(__float_as_uint(a[3])),
                   "r"(__float_as_uint(b[0])), "r"(__float_as_uint(b[1])));
}
__device__ __forceinline__ void mmaf16(float (&d)[4], const uint32_t* a, uint32_t b0, uint32_t b1) {
    asm volatile("mma.sync.aligned.m16n8k16.row.col.f32.f16.f16.f32 "
                 "{%0,%1,%2,%3}, {%4,%5,%6,%7}, {%8,%9}, {%0,%1,%2,%3};\n"
                 : "+f"(d[0]), "+f"(d[1]), "+f"(d[2]), "+f"(d[3])
                 : "r"(a[0]), "r"(a[1]), "r"(a[2]), "r"(a[3]), "r"(b0), "r"(b1));
}
__device__ __forceinline__ void ldsm4(uint32_t& r0, uint32_t& r1, uint32_t& r2, uint32_t& r3, uint32_t a) {
    asm volatile("ldmatrix.sync.aligned.m8n8.x4.shared.b16 {%0,%1,%2,%3}, [%4];\n"
                 : "=r"(r0), "=r"(r1), "=r"(r2), "=r"(r3) : "r"(a));
}
__device__ __forceinline__ void ldsm4t(uint32_t& r0, uint32_t& r1, uint32_t& r2, uint32_t& r3, uint32_t a) {
    asm volatile("ldmatrix.sync.aligned.m8n8.x4.trans.shared.b16 {%0,%1,%2,%3}, [%4];\n"
                 : "=r"(r0), "=r"(r1), "=r"(r2), "=r"(r3) : "r"(a));
}
__device__ __forceinline__ uint32_t packh2(float lo, float hi) {
    __half2 h = __floats2half2_rn(lo, hi);
    return *reinterpret_cast<uint32_t*>(&h);
}
__device__ __forceinline__ void cpa16(uint32_t dst, const void* src) {
    asm volatile("cp.async.cg.shared.global [%0], [%1], 16;" :: "r"(dst), "l"(src));
}
#define CP_COMMIT asm volatile("cp.async.commit_group;")
#define CP_WAIT1  asm volatile("cp.async.wait_group 1;")
#define CP_WAIT0  asm volatile("cp.async.wait_group 0;")

// ---------------------------------------------------------------------------
// GroupNorm
// ---------------------------------------------------------------------------
__global__ __launch_bounds__(512) void gn_kernel(const float* __restrict__ x,
                                                 const float* __restrict__ gamma,
                                                 const float* __restrict__ beta,
                                                 float* __restrict__ hout) {
    int b = blockIdx.x >> 5;
    int g = blockIdx.x & 31;
    const float4* xp = (const float4*)(x    + ((size_t)b * C_ + g * GC) * NSP);
    float4*       hp = (float4*)      (hout + ((size_t)b * C_ + g * GC) * NSP);
    int tid = threadIdx.x;

    float s = 0.f, ss = 0.f;
    float4 v[8];
    #pragma unroll
    for (int i = 0; i < 8; i++) {
        v[i] = xp[tid + i * 512];
        s  += v[i].x + v[i].y + v[i].z + v[i].w;
        ss += v[i].x * v[i].x + v[i].y * v[i].y + v[i].z * v[i].z + v[i].w * v[i].w;
    }
    __shared__ float rs[512], rss[512];
    rs[tid] = s; rss[tid] = ss;
    __syncthreads();
    for (int off = 256; off > 0; off >>= 1) {
        if (tid < off) { rs[tid] += rs[tid + off]; rss[tid] += rss[tid + off]; }
        __syncthreads();
    }
    const float invn = 1.f / (GC * NSP);
    float mean = rs[0] * invn;
    float var  = rss[0] * invn - mean * mean;
    float inv  = rsqrtf(var + 1e-5f);

    #pragma unroll
    for (int i = 0; i < 8; i++) {
        int idx = tid + i * 512;
        int cl = idx >> 8;
        float ga = gamma[g * GC + cl] * inv;
        float be = beta [g * GC + cl];
        float4 o;
        o.x = (v[i].x - mean) * ga + be;
        o.y = (v[i].y - mean) * ga + be;
        o.z = (v[i].z - mean) * ga + be;
        o.w = (v[i].w - mean) * ga + be;
        hp[idx] = o;
    }
}

// ---------------------------------------------------------------------------
// tf32 batched GEMM with cp.async double buffering; raw fp32 bits fed to
// tf32 mma (HW truncation, no cvt). Out = W @ H + bias (+X) or fp16 OutH.
// ---------------------------------------------------------------------------
__global__ __launch_bounds__(256, 2) void gemm_tf32(const float* __restrict__ W,
                                                    const float* __restrict__ Hin,
                                                    const float* __restrict__ bias,
                                                    const float* __restrict__ X,
                                                    float* __restrict__ Out,
                                                    __half* __restrict__ OutH) {
    __shared__ float As[2][128][20];
    __shared__ float Bs[2][16][136];

    const int M = gridDim.y * 128;
    const float* Hb = Hin + (size_t)blockIdx.z * C_ * NSP;
    int m0 = blockIdx.y * 128, n0 = blockIdx.x * 128;
    int tid = threadIdx.x;
    int w = tid >> 5, lane = tid & 31;
    int r = lane >> 2, c = lane & 3;
    int wm = (w & 3) * 32, wn = (w >> 2) * 64;

    uint32_t as0 = (uint32_t)__cvta_generic_to_shared(&As[0][0][0]);
    uint32_t bs0 = (uint32_t)__cvta_generic_to_shared(&Bs[0][0][0]);

    // loader indices
    int ar0 = tid >> 2,       ap0 = (tid & 3) * 4;          // chunk tid
    int ar1 = (tid + 256) >> 2, ap1 = ((tid + 256) & 3) * 4; // chunk tid+256
    int br0 = tid >> 5,       bp0 = (tid & 31) * 4;
    int br1 = (tid + 256) >> 5, bp1 = ((tid + 256) & 31) * 4;

    auto issue = [&](int c0, int s) {
        cpa16(as0 + ((s * 128 + ar0) * 20 + ap0) * 4, &W[(size_t)(m0 + ar0) * C_ + c0 + ap0]);
        cpa16(as0 + ((s * 128 + ar1) * 20 + ap1) * 4, &W[(size_t)(m0 + ar1) * C_ + c0 + ap1]);
        cpa16(bs0 + ((s * 16 + br0) * 136 + bp0) * 4, &Hb[(size_t)(c0 + br0) * NSP + n0 + bp0]);
        cpa16(bs0 + ((s * 16 + br1) * 136 + bp1) * 4, &Hb[(size_t)(c0 + br1) * NSP + n0 + bp1]);
        CP_COMMIT;
    };

    float acc[2][8][4];
    #pragma unroll
    for (int i = 0; i < 2; i++)
        #pragma unroll
        for (int j = 0; j < 8; j++)
            #pragma unroll
            for (int k = 0; k < 4; k++) acc[i][j][k] = 0.f;

    issue(0, 0);

    for (int ch = 0; ch < 32; ch++) {
        int s = ch & 1;
        if (ch < 31) {
            __syncthreads();               // protect buf being overwritten
            issue((ch + 1) * 16, s ^ 1);
            CP_WAIT1;
        } else {
            CP_WAIT0;
        }
        __syncthreads();

        #pragma unroll
        for (int ks = 0; ks < 16; ks += 8) {
            float a[2][4];
            #pragma unroll
            for (int i = 0; i < 2; i++) {
                a[i][0] = As[s][wm + i * 16 + r][ks + c];
                a[i][1] = As[s][wm + i * 16 + r + 8][ks + c];
                a[i][2] = As[s][wm + i * 16 + r][ks + c + 4];
                a[i][3] = As[s][wm + i * 16 + r + 8][ks + c + 4];
            }
            #pragma unroll
            for (int j = 0; j < 8; j++) {
                float b[2];
                b[0] = Bs[s][ks + c][wn + j * 8 + r];
                b[1] = Bs[s][ks + c + 4][wn + j * 8 + r];
                mma8(acc[0][j], a[0], b);
                mma8(acc[1][j], a[1], b);
            }
        }
    }

    #pragma unroll
    for (int i = 0; i < 2; i++) {
        int mrow = m0 + wm + i * 16 + r;
        float bv0 = bias[mrow], bv1 = bias[mrow + 8];
        #pragma unroll
        for (int j = 0; j < 8; j++) {
            int col = n0 + wn + j * 8 + 2 * c;
            size_t i0 = (size_t)mrow * NSP + col;
            size_t i1 = (size_t)(mrow + 8) * NSP + col;
            float2 v0 = {acc[i][j][0] + bv0, acc[i][j][1] + bv0};
            float2 v1 = {acc[i][j][2] + bv1, acc[i][j][3] + bv1};
            if (OutH) {
                __half* OHb = OutH + (size_t)blockIdx.z * M * NSP;
                *(__half2*)&OHb[i0] = __floats2half2_rn(v0.x, v0.y);
                *(__half2*)&OHb[i1] = __floats2half2_rn(v1.x, v1.y);
            } else {
                const float* Xb = X ? (X + (size_t)blockIdx.z * M * NSP) : nullptr;
                float*       Ob = Out + (size_t)blockIdx.z * M * NSP;
                if (Xb) {
                    float2 x0 = *(const float2*)&Xb[i0];
                    float2 x1 = *(const float2*)&Xb[i1];
                    v0.x += x0.x; v0.y += x0.y;
                    v1.x += x1.x; v1.y += x1.y;
                }
                *(float2*)&Ob[i0] = v0;
                *(float2*)&Ob[i1] = v1;
            }
        }
    }
}

// ---------------------------------------------------------------------------
// fp16 flash attention, cp.async double-buffered K/V (no register prefetch).
// smem: Q[64][136] | K0[64][72] V0[64][72] | K1[64][72] V1[64][72]  = 54272 B
// ---------------------------------------------------------------------------
#define ATTN_SMEM 54272

__global__ __launch_bounds__(256, 2) void attn_f16(const __half* __restrict__ qkv,
                                                   float* __restrict__ ao) {
    extern __shared__ char smc[];
    __half* Qs = (__half*)smc;
    float*  Osm = (float*)smc;

    int qt = blockIdx.x, hh = blockIdx.y, b = blockIdx.z;
    const __half* qb = qkv + ((size_t)b * (3 * C_) + hh * HD) * NSP;
    const __half* kb = qb + (size_t)C_ * NSP;
    const __half* vb = qb + (size_t)2 * C_ * NSP;
    int n0 = qt * 128;
    int tid = threadIdx.x, w = tid >> 5, l = tid & 31;
    int r = l >> 2, c = l & 3;
    int prow = w * 16;

    // Load Q tile
    #pragma unroll
    for (int i = 0; i < 8; i++) {
        int f = tid + i * 256;
        int d = f >> 5, n4 = (f & 31) * 4;
        *(uint2*)&Qs[d * 136 + n4] = *(const uint2*)&qb[(size_t)d * NSP + n0 + n4];
    }

    uint32_t smb = (uint32_t)__cvta_generic_to_shared(smc);
    uint32_t qs0 = smb;
    uint32_t kbuf[2] = {smb + 17408, smb + 35840};
    // ldmatrix lane addresses
    uint32_t qa = qs0 + (((l & 7) + (l >> 4) * 8) * 136 + prow + ((l >> 3) & 1) * 8) * 2;
    uint32_t koff = (((l & 7) + ((l >> 3) & 1) * 8) * 72 + (l >> 4) * 8) * 2;
    uint32_t voff = 9216 + (((l & 7) + (l >> 4) * 8) * 72 + ((l >> 3) & 1) * 8) * 2;

    // cp.async loader: K tile 512 x 16B chunks, V same; 2 chunks each per thread
    int cr0 = tid >> 3,        cc0 = (tid & 7) * 8;
    int cr1 = (tid + 256) >> 3, cc1 = ((tid + 256) & 7) * 8;

    auto issue = [&](int kt, int s) {
        int mk0 = kt * 64;
        uint32_t kd = kbuf[s];
        cpa16(kd + (cr0 * 72 + cc0) * 2,        &kb[(size_t)cr0 * NSP + mk0 + cc0]);
        cpa16(kd + (cr1 * 72 + cc1) * 2,        &kb[(size_t)cr1 * NSP + mk0 + cc1]);
        cpa16(kd + 9216 + (cr0 * 72 + cc0) * 2, &vb[(size_t)cr0 * NSP + mk0 + cc0]);
        cpa16(kd + 9216 + (cr1 * 72 + cc1) * 2, &vb[(size_t)cr1 * NSP + mk0 + cc1]);
        CP_COMMIT;
    };

    float o[8][4];
    #pragma unroll
    for (int j = 0; j < 8; j++)
        #pragma unroll
        for (int k = 0; k < 4; k++) o[j][k] = 0.f;
    float osum[4] = {0.f, 0.f, 0.f, 0.f};
    float mr0 = -1e30f, mr1 = -1e30f;
    const float csc = 0.125f * 1.4426950408889634f;
    const uint32_t ONE2 = 0x3C003C00u;

    issue(0, 0);

    for (int kt = 0; kt < 16; kt++) {
        int s = kt & 1;
        if (kt < 15) {
            __syncthreads();
            issue(kt + 1, s ^ 1);
            CP_WAIT1;
        } else {
            CP_WAIT0;
        }
        __syncthreads();
        uint32_t ka = kbuf[s] + koff;
        uint32_t va = kbuf[s] + voff;

        // S = Q^T K
        float sc[8][4];
        #pragma unroll
        for (int j = 0; j < 8; j++)
            #pragma unroll
            for (int k = 0; k < 4; k++) sc[j][k] = 0.f;
        #pragma unroll
        for (int dk = 0; dk < 4; dk++) {
            uint32_t a[4];
            ldsm4t(a[0], a[1], a[2], a[3], qa + dk * 16 * 272);
            #pragma unroll
            for (int jj = 0; jj < 4; jj++) {
                uint32_t bq[4];
                ldsm4t(bq[0], bq[1], bq[2], bq[3], ka + dk * 16 * 144 + jj * 32);
                mmaf16(sc[2 * jj], a, bq[0], bq[1]);
                mmaf16(sc[2 * jj + 1], a, bq[2], bq[3]);
            }
        }

        // Online softmax
        float tm0 = -1e30f, tm1 = -1e30f;
        #pragma unroll
        for (int j = 0; j < 8; j++) {
            tm0 = fmaxf(tm0, fmaxf(sc[j][0], sc[j][1]));
            tm1 = fmaxf(tm1, fmaxf(sc[j][2], sc[j][3]));
        }
        tm0 = fmaxf(tm0, __shfl_xor_sync(0xffffffffu, tm0, 1));
        tm0 = fmaxf(tm0, __shfl_xor_sync(0xffffffffu, tm0, 2));
        tm1 = fmaxf(tm1, __shfl_xor_sync(0xffffffffu, tm1, 1));
        tm1 = fmaxf(tm1, __shfl_xor_sync(0xffffffffu, tm1, 2));
        float nm0 = fmaxf(mr0, tm0), nm1 = fmaxf(mr1, tm1);
        float cr0f = ex2((mr0 - nm0) * csc), cr1f = ex2((mr1 - nm1) * csc);
        mr0 = nm0; mr1 = nm1;
        float b0 = nm0 * csc, b1 = nm1 * csc;

        // P = exp2(s*csc - b), fp16x2 fragments
        uint32_t ph[16];
        #pragma unroll
        for (int q = 0; q < 8; q++) {
            ph[2 * q]     = h2ex2(packh2(fmaf(sc[q][0], csc, -b0), fmaf(sc[q][1], csc, -b0)));
            ph[2 * q + 1] = h2ex2(packh2(fmaf(sc[q][2], csc, -b1), fmaf(sc[q][3], csc, -b1)));
        }

        // Rescale
        #pragma unroll
        for (int j = 0; j < 8; j++) {
            o[j][0] *= cr0f; o[j][1] *= cr0f;
            o[j][2] *= cr1f; o[j][3] *= cr1f;
        }
        osum[0] *= cr0f; osum[1] *= cr0f; osum[2] *= cr1f; osum[3] *= cr1f;

        // O += P @ V^T ; osum += P @ ones
        #pragma unroll
        for (int kk = 0; kk < 4; kk++) {
            mmaf16(osum, &ph[4 * kk], ONE2, ONE2);
            #pragma unroll
            for (int dd = 0; dd < 4; dd++) {
                uint32_t bv[4];
                ldsm4(bv[0], bv[1], bv[2], bv[3], va + dd * 16 * 144 + kk * 32);
                mmaf16(o[2 * dd],     &ph[4 * kk], bv[0], bv[1]);
                mmaf16(o[2 * dd + 1], &ph[4 * kk], bv[2], bv[3]);
            }
        }
    }

    // Epilogue
    float il0 = 1.f / osum[0], il1 = 1.f / osum[2];
    __syncthreads();
    #pragma unroll
    for (int j = 0; j < 8; j++) {
        int d = 8 * j + 2 * c;
        Osm[(d)     * 136 + prow + r]     = o[j][0] * il0;
        Osm[(d + 1) * 136 + prow + r]     = o[j][1] * il0;
        Osm[(d)     * 136 + prow + r + 8] = o[j][2] * il1;
        Osm[(d + 1) * 136 + prow + r + 8] = o[j][3] * il1;
    }
    __syncthreads();
    float* aob = ao + ((size_t)b * C_ + hh * HD) * NSP;
    #pragma unroll
    for (int i = 0; i < 8; i++) {
        int f = tid + i * 256;
        int d = f >> 5, n4 = (f & 31) * 4;
        *(float4*)&aob[(size_t)d * NSP + n0 + n4] = *(float4*)&Osm[d * 136 + n4];
    }
}

// ---------------------------------------------------------------------------
extern "C" void kernel_launch(void* const* d_in, const int* in_sizes, int n_in,
                              void* d_out, int out_size) {
    const float* x      = (const float*)d_in[0];
    const float* gamma  = (const float*)d_in[1];
    const float* beta   = (const float*)d_in[2];
    const float* w_qkv  = (const float*)d_in[3];
    const float* b_qkv  = (const float*)d_in[4];
    const float* w_proj = (const float*)d_in[5];
    const float* b_proj = (const float*)d_in[6];
    float* out = (float*)d_out;

    float *ph, *pa;
    __half* pq;
    cudaGetSymbolAddress((void**)&ph, g_h);
    cudaGetSymbolAddress((void**)&pq, g_qkv);
    cudaGetSymbolAddress((void**)&pa, g_ao);

    cudaFuncSetAttribute(attn_f16, cudaFuncAttributeMaxDynamicSharedMemorySize, ATTN_SMEM);

    gn_kernel<<<B_ * NG, 512>>>(x, gamma, beta, ph);
    gemm_tf32<<<dim3(8, 12, 16), 256>>>(w_qkv, ph, b_qkv, nullptr, nullptr, pq);
    attn_f16<<<dim3(8, NH, B_), 256, ATTN_SMEM>>>(pq, pa);
    gemm_tf32<<<dim3(8, 4, 16), 256>>>(w_proj, pa, b_proj, x, out, nullptr);
}

// round 6
// speedup vs baseline: 7.4003x; 1.4390x over previous
#include <cuda_runtime.h>
#include <cuda_fp16.h>
#include <math.h>
#include <stdint.h>

#define B_   16
#define C_   512
#define NSP  1024
#define NG   32
#define GC   16
#define NH   8
#define HD   64

__device__ __half g_h   [(size_t)B_ * C_ * NSP];
__device__ __half g_qkv [(size_t)B_ * 3 * C_ * NSP];
__device__ __half g_ao  [(size_t)B_ * C_ * NSP];
__device__ __half g_wqkv[(size_t)3 * C_ * C_];
__device__ __half g_wprj[(size_t)C_ * C_];

__device__ __forceinline__ float ex2(float x) {
    float y;
    asm("ex2.approx.ftz.f32 %0, %1;" : "=f"(y) : "f"(x));
    return y;
}
__device__ __forceinline__ uint32_t h2ex2(uint32_t x) {
    uint32_t y;
    asm("ex2.approx.f16x2 %0, %1;" : "=r"(y) : "r"(x));
    return y;
}
__device__ __forceinline__ void mmaf16(float (&d)[4], const uint32_t* a, uint32_t b0, uint32_t b1) {
    asm volatile("mma.sync.aligned.m16n8k16.row.col.f32.f16.f16.f32 "
                 "{%0,%1,%2,%3}, {%4,%5,%6,%7}, {%8,%9}, {%0,%1,%2,%3};\n"
                 : "+f"(d[0]), "+f"(d[1]), "+f"(d[2]), "+f"(d[3])
                 : "r"(a[0]), "r"(a[1]), "r"(a[2]), "r"(a[3]), "r"(b0), "r"(b1));
}
__device__ __forceinline__ void ldsm4(uint32_t& r0, uint32_t& r1, uint32_t& r2, uint32_t& r3, uint32_t a) {
    asm volatile("ldmatrix.sync.aligned.m8n8.x4.shared.b16 {%0,%1,%2,%3}, [%4];\n"
                 : "=r"(r0), "=r"(r1), "=r"(r2), "=r"(r3) : "r"(a));
}
__device__ __forceinline__ void ldsm4t(uint32_t& r0, uint32_t& r1, uint32_t& r2, uint32_t& r3, uint32_t a) {
    asm volatile("ldmatrix.sync.aligned.m8n8.x4.trans.shared.b16 {%0,%1,%2,%3}, [%4];\n"
                 : "=r"(r0), "=r"(r1), "=r"(r2), "=r"(r3) : "r"(a));
}
__device__ __forceinline__ uint32_t packh2(float lo, float hi) {
    __half2 h = __floats2half2_rn(lo, hi);
    return *reinterpret_cast<uint32_t*>(&h);
}
__device__ __forceinline__ void cpa16(uint32_t dst, const void* src) {
    asm volatile("cp.async.cg.shared.global [%0], [%1], 16;" :: "r"(dst), "l"(src));
}
#define CP_COMMIT asm volatile("cp.async.commit_group;")
#define CP_WAIT1  asm volatile("cp.async.wait_group 1;")
#define CP_WAIT0  asm volatile("cp.async.wait_group 0;")

// ---------------------------------------------------------------------------
// Weight conversion fp32 -> fp16 (runs each replay; deterministic)
// ---------------------------------------------------------------------------
__global__ __launch_bounds__(256) void conv_kernel(const float* __restrict__ a,
                                                   __half* __restrict__ b, int n4) {
    int i = blockIdx.x * 256 + threadIdx.x;
    if (i < n4) {
        float4 v = ((const float4*)a)[i];
        uint2 o;
        o.x = packh2(v.x, v.y);
        o.y = packh2(v.z, v.w);
        ((uint2*)b)[i] = o;
    }
}

// ---------------------------------------------------------------------------
// GroupNorm: fp32 in, fp16 out
// ---------------------------------------------------------------------------
__global__ __launch_bounds__(512) void gn_kernel(const float* __restrict__ x,
                                                 const float* __restrict__ gamma,
                                                 const float* __restrict__ beta,
                                                 __half* __restrict__ hout) {
    int b = blockIdx.x >> 5;
    int g = blockIdx.x & 31;
    const float4* xp = (const float4*)(x + ((size_t)b * C_ + g * GC) * NSP);
    uint2* hp = (uint2*)(hout + ((size_t)b * C_ + g * GC) * NSP);
    int tid = threadIdx.x;

    float s = 0.f, ss = 0.f;
    float4 v[8];
    #pragma unroll
    for (int i = 0; i < 8; i++) {
        v[i] = xp[tid + i * 512];
        s  += v[i].x + v[i].y + v[i].z + v[i].w;
        ss += v[i].x * v[i].x + v[i].y * v[i].y + v[i].z * v[i].z + v[i].w * v[i].w;
    }
    __shared__ float rs[512], rss[512];
    rs[tid] = s; rss[tid] = ss;
    __syncthreads();
    for (int off = 256; off > 0; off >>= 1) {
        if (tid < off) { rs[tid] += rs[tid + off]; rss[tid] += rss[tid + off]; }
        __syncthreads();
    }
    const float invn = 1.f / (GC * NSP);
    float mean = rs[0] * invn;
    float var  = rss[0] * invn - mean * mean;
    float inv  = rsqrtf(var + 1e-5f);

    #pragma unroll
    for (int i = 0; i < 8; i++) {
        int idx = tid + i * 512;
        int cl = idx >> 8;
        float ga = gamma[g * GC + cl] * inv;
        float be = beta [g * GC + cl];
        uint2 o;
        o.x = packh2((v[i].x - mean) * ga + be, (v[i].y - mean) * ga + be);
        o.y = packh2((v[i].z - mean) * ga + be, (v[i].w - mean) * ga + be);
        hp[idx] = o;
    }
}

// ---------------------------------------------------------------------------
// fp16 batched GEMM, cp.async double buffered. Out[b][m][n] = W@H + bias (+X).
// Block 128x128, k-chunk 32. 8 warps, warp tile 32x64.
// A smem [m][40] fp16, B smem [k][136] fp16 (both ldsm conflict-free).
// ---------------------------------------------------------------------------
__global__ __launch_bounds__(256, 2) void gemm_f16(const __half* __restrict__ W,
                                                   const __half* __restrict__ Hin,
                                                   const float* __restrict__ bias,
                                                   const float* __restrict__ X,
                                                   float* __restrict__ Out,
                                                   __half* __restrict__ OutH) {
    __shared__ __half As[2][128][40];
    __shared__ __half Bs[2][32][136];

    const int M = gridDim.y * 128;
    const __half* Hb = Hin + (size_t)blockIdx.z * C_ * NSP;
    int m0 = blockIdx.y * 128, n0 = blockIdx.x * 128;
    int tid = threadIdx.x;
    int w = tid >> 5, l = tid & 31;
    int r = l >> 2, c = l & 3;
    int wm = (w & 3) * 32, wn = (w >> 2) * 64;

    uint32_t as0 = (uint32_t)__cvta_generic_to_shared(&As[0][0][0]);
    uint32_t bs0 = (uint32_t)__cvta_generic_to_shared(&Bs[0][0][0]);

    // loaders: A 128x32 halves = 512 chunks of 8; B 32x128 = 512 chunks
    int ar0 = tid >> 1,         ac0 = (tid & 1) * 8;        // no: 128x32/8=512, 2/thread
    int ar1 = (tid + 256) >> 1, ac1 = ((tid + 256) & 1) * 8;
    int br0 = tid >> 4,         bc0 = (tid & 15) * 8;
    int br1 = (tid + 256) >> 4, bc1 = ((tid + 256) & 15) * 8;
    // fix A mapping: 32 halves per row = 4 chunks of 8: row = idx>>2, col=(idx&3)*8
    ar0 = tid >> 2;         ac0 = (tid & 3) * 8;
    ar1 = (tid + 256) >> 2; ac1 = ((tid + 256) & 3) * 8;

    auto issue = [&](int c0, int s) {
        cpa16(as0 + ((s * 128 + ar0) * 40 + ac0) * 2, &W[(size_t)(m0 + ar0) * C_ + c0 + ac0]);
        cpa16(as0 + ((s * 128 + ar1) * 40 + ac1) * 2, &W[(size_t)(m0 + ar1) * C_ + c0 + ac1]);
        cpa16(bs0 + ((s * 32 + br0) * 136 + bc0) * 2, &Hb[(size_t)(c0 + br0) * NSP + n0 + bc0]);
        cpa16(bs0 + ((s * 32 + br1) * 136 + bc1) * 2, &Hb[(size_t)(c0 + br1) * NSP + n0 + bc1]);
        CP_COMMIT;
    };

    // ldsm lane addresses
    // A (non-trans): row = wm + i*16 + (l&15), col = ks*16 + (l>>4)*8
    uint32_t aoff = ((wm + (l & 15)) * 40 + (l >> 4) * 8) * 2;
    // B (trans): row = ks*16 + (l&7) + ((l>>3)&1)*8, col = wn + j*16 + (l>>4)*8
    uint32_t boff = (((l & 7) + ((l >> 3) & 1) * 8) * 136 + wn + (l >> 4) * 8) * 2;

    float acc[2][8][4];
    #pragma unroll
    for (int i = 0; i < 2; i++)
        #pragma unroll
        for (int j = 0; j < 8; j++)
            #pragma unroll
            for (int k = 0; k < 4; k++) acc[i][j][k] = 0.f;

    issue(0, 0);

    for (int ch = 0; ch < 16; ch++) {
        int s = ch & 1;
        if (ch < 15) {
            __syncthreads();
            issue((ch + 1) * 32, s ^ 1);
            CP_WAIT1;
        } else {
            CP_WAIT0;
        }
        __syncthreads();
        uint32_t ab = as0 + (uint32_t)(s * 128 * 40 * 2);
        uint32_t bb = bs0 + (uint32_t)(s * 32 * 136 * 2);

        #pragma unroll
        for (int ks = 0; ks < 2; ks++) {
            uint32_t a0[4], a1[4];
            ldsm4(a0[0], a0[1], a0[2], a0[3], ab + aoff + ks * 32);
            ldsm4(a1[0], a1[1], a1[2], a1[3], ab + aoff + 16 * 80 + ks * 32);
            #pragma unroll
            for (int j = 0; j < 4; j++) {
                uint32_t bq[4];
                ldsm4t(bq[0], bq[1], bq[2], bq[3], bb + boff + ks * 16 * 272 + j * 32);
                mmaf16(acc[0][2 * j],     a0, bq[0], bq[1]);
                mmaf16(acc[0][2 * j + 1], a0, bq[2], bq[3]);
                mmaf16(acc[1][2 * j],     a1, bq[0], bq[1]);
                mmaf16(acc[1][2 * j + 1], a1, bq[2], bq[3]);
            }
        }
    }

    #pragma unroll
    for (int i = 0; i < 2; i++) {
        int mrow = m0 + wm + i * 16 + r;
        float bv0 = bias[mrow], bv1 = bias[mrow + 8];
        #pragma unroll
        for (int j = 0; j < 8; j++) {
            int col = n0 + wn + j * 8 + 2 * c;
            size_t i0 = (size_t)mrow * NSP + col;
            size_t i1 = (size_t)(mrow + 8) * NSP + col;
            float2 v0 = {acc[i][j][0] + bv0, acc[i][j][1] + bv0};
            float2 v1 = {acc[i][j][2] + bv1, acc[i][j][3] + bv1};
            if (OutH) {
                __half* OHb = OutH + (size_t)blockIdx.z * M * NSP;
                *(uint32_t*)&OHb[i0] = packh2(v0.x, v0.y);
                *(uint32_t*)&OHb[i1] = packh2(v1.x, v1.y);
            } else {
                const float* Xb = X + (size_t)blockIdx.z * M * NSP;
                float*       Ob = Out + (size_t)blockIdx.z * M * NSP;
                float2 x0 = *(const float2*)&Xb[i0];
                float2 x1 = *(const float2*)&Xb[i1];
                v0.x += x0.x; v0.y += x0.y;
                v1.x += x1.x; v1.y += x1.y;
                *(float2*)&Ob[i0] = v0;
                *(float2*)&Ob[i1] = v1;
            }
        }
    }
}

// ---------------------------------------------------------------------------
// fp16 flash attention. Block = 64 queries, 128 threads (4 warps), 4 CTAs/SM.
// smem: Q[64][72] | K0|V0 | K1|V1 (each [64][72]) = 46080 B
// Output ao fp16.
// ---------------------------------------------------------------------------
#define ATTN_SMEM 46080

__global__ __launch_bounds__(128, 4) void attn_f16(const __half* __restrict__ qkv,
                                                   __half* __restrict__ ao) {
    extern __shared__ char smc[];
    __half* Qs = (__half*)smc;

    int qt = blockIdx.x, hh = blockIdx.y, b = blockIdx.z;
    const __half* qb = qkv + ((size_t)b * (3 * C_) + hh * HD) * NSP;
    const __half* kb = qb + (size_t)C_ * NSP;
    const __half* vb = qb + (size_t)2 * C_ * NSP;
    int n0 = qt * 64;
    int tid = threadIdx.x, w = tid >> 5, l = tid & 31;
    int r = l >> 2, c = l & 3;
    int prow = w * 16;

    // Load Q tile [64 d][64 q]
    #pragma unroll
    for (int i = 0; i < 8; i++) {
        int f = tid + i * 128;
        int d = f >> 4, n4 = (f & 15) * 4;
        *(uint2*)&Qs[d * 72 + n4] = *(const uint2*)&qb[(size_t)d * NSP + n0 + n4];
    }

    uint32_t smb = (uint32_t)__cvta_generic_to_shared(smc);
    uint32_t kbuf[2] = {smb + 9216, smb + 27648};
    uint32_t qa   = smb + (((l & 7) + (l >> 4) * 8) * 72 + prow + ((l >> 3) & 1) * 8) * 2;
    uint32_t koff = (((l & 7) + ((l >> 3) & 1) * 8) * 72 + (l >> 4) * 8) * 2;
    uint32_t voff = 9216 + (((l & 7) + (l >> 4) * 8) * 72 + ((l >> 3) & 1) * 8) * 2;

    int cr = tid >> 3, cc = (tid & 7) * 8;   // 64 rows x 8 chunks, 128 thr -> 4/half... (512 chunks /128 = 4 each)
    auto issue = [&](int kt, int s) {
        int mk0 = kt * 64;
        uint32_t kd = kbuf[s];
        #pragma unroll
        for (int i = 0; i < 4; i++) {
            int row = cr + i * 16;
            cpa16(kd + (row * 72 + cc) * 2,        &kb[(size_t)row * NSP + mk0 + cc]);
            cpa16(kd + 9216 + (row * 72 + cc) * 2, &vb[(size_t)row * NSP + mk0 + cc]);
        }
        CP_COMMIT;
    };

    float o[8][4];
    #pragma unroll
    for (int j = 0; j < 8; j++)
        #pragma unroll
        for (int k = 0; k < 4; k++) o[j][k] = 0.f;
    float osum[4] = {0.f, 0.f, 0.f, 0.f};
    float mr0 = -1e30f, mr1 = -1e30f;
    const float csc = 0.125f * 1.4426950408889634f;
    const uint32_t ONE2 = 0x3C003C00u;

    issue(0, 0);

    for (int kt = 0; kt < 16; kt++) {
        int s = kt & 1;
        if (kt < 15) {
            __syncthreads();
            issue(kt + 1, s ^ 1);
            CP_WAIT1;
        } else {
            CP_WAIT0;
        }
        __syncthreads();
        uint32_t ka = kbuf[s] + koff;
        uint32_t va = kbuf[s] + voff;

        // S = Q^T K : 16 rows x 64 keys
        float sc[8][4];
        #pragma unroll
        for (int j = 0; j < 8; j++)
            #pragma unroll
            for (int k = 0; k < 4; k++) sc[j][k] = 0.f;
        #pragma unroll
        for (int dk = 0; dk < 4; dk++) {
            uint32_t a[4];
            ldsm4t(a[0], a[1], a[2], a[3], qa + dk * 16 * 144);
            #pragma unroll
            for (int jj = 0; jj < 4; jj++) {
                uint32_t bq[4];
                ldsm4t(bq[0], bq[1], bq[2], bq[3], ka + dk * 16 * 144 + jj * 32);
                mmaf16(sc[2 * jj], a, bq[0], bq[1]);
                mmaf16(sc[2 * jj + 1], a, bq[2], bq[3]);
            }
        }

        // Online softmax
        float tm0 = -1e30f, tm1 = -1e30f;
        #pragma unroll
        for (int j = 0; j < 8; j++) {
            tm0 = fmaxf(tm0, fmaxf(sc[j][0], sc[j][1]));
            tm1 = fmaxf(tm1, fmaxf(sc[j][2], sc[j][3]));
        }
        tm0 = fmaxf(tm0, __shfl_xor_sync(0xffffffffu, tm0, 1));
        tm0 = fmaxf(tm0, __shfl_xor_sync(0xffffffffu, tm0, 2));
        tm1 = fmaxf(tm1, __shfl_xor_sync(0xffffffffu, tm1, 1));
        tm1 = fmaxf(tm1, __shfl_xor_sync(0xffffffffu, tm1, 2));
        float nm0 = fmaxf(mr0, tm0), nm1 = fmaxf(mr1, tm1);
        float cr0f = ex2((mr0 - nm0) * csc), cr1f = ex2((mr1 - nm1) * csc);
        mr0 = nm0; mr1 = nm1;
        float b0 = nm0 * csc, b1 = nm1 * csc;

        uint32_t ph[16];
        #pragma unroll
        for (int q = 0; q < 8; q++) {
            ph[2 * q]     = h2ex2(packh2(fmaf(sc[q][0], csc, -b0), fmaf(sc[q][1], csc, -b0)));
            ph[2 * q + 1] = h2ex2(packh2(fmaf(sc[q][2], csc, -b1), fmaf(sc[q][3], csc, -b1)));
        }

        #pragma unroll
        for (int j = 0; j < 8; j++) {
            o[j][0] *= cr0f; o[j][1] *= cr0f;
            o[j][2] *= cr1f; o[j][3] *= cr1f;
        }
        osum[0] *= cr0f; osum[1] *= cr0f; osum[2] *= cr1f; osum[3] *= cr1f;

        #pragma unroll
        for (int kk = 0; kk < 4; kk++) {
            mmaf16(osum, &ph[4 * kk], ONE2, ONE2);
            #pragma unroll
            for (int dd = 0; dd < 4; dd++) {
                uint32_t bv[4];
                ldsm4(bv[0], bv[1], bv[2], bv[3], va + dd * 16 * 144 + kk * 32);
                mmaf16(o[2 * dd],     &ph[4 * kk], bv[0], bv[1]);
                mmaf16(o[2 * dd + 1], &ph[4 * kk], bv[2], bv[3]);
            }
        }
    }

    // Epilogue: normalize, transpose via smem (fp16), coalesced store
    float il0 = 1.f / osum[0], il1 = 1.f / osum[2];
    __syncthreads();
    __half* Osm = (__half*)smc;   // [64][72]
    #pragma unroll
    for (int j = 0; j < 8; j++) {
        int d = 8 * j + 2 * c;
        Osm[(d)     * 72 + prow + r]     = __float2half(o[j][0] * il0);
        Osm[(d + 1) * 72 + prow + r]     = __float2half(o[j][1] * il0);
        Osm[(d)     * 72 + prow + r + 8] = __float2half(o[j][2] * il1);
        Osm[(d + 1) * 72 + prow + r + 8] = __float2half(o[j][3] * il1);
    }
    __syncthreads();
    __half* aob = ao + ((size_t)b * C_ + hh * HD) * NSP;
    #pragma unroll
    for (int i = 0; i < 8; i++) {
        int f = tid + i * 128;
        int d = f >> 4, n4 = (f & 15) * 4;
        *(uint2*)&aob[(size_t)d * NSP + n0 + n4] = *(uint2*)&Osm[d * 72 + n4];
    }
}

// ---------------------------------------------------------------------------
extern "C" void kernel_launch(void* const* d_in, const int* in_sizes, int n_in,
                              void* d_out, int out_size) {
    const float* x      = (const float*)d_in[0];
    const float* gamma  = (const float*)d_in[1];
    const float* beta   = (const float*)d_in[2];
    const float* w_qkv  = (const float*)d_in[3];
    const float* b_qkv  = (const float*)d_in[4];
    const float* w_proj = (const float*)d_in[5];
    const float* b_proj = (const float*)d_in[6];
    float* out = (float*)d_out;

    __half *ph, *pq, *pa, *pwq, *pwp;
    cudaGetSymbolAddress((void**)&ph,  g_h);
    cudaGetSymbolAddress((void**)&pq,  g_qkv);
    cudaGetSymbolAddress((void**)&pa,  g_ao);
    cudaGetSymbolAddress((void**)&pwq, g_wqkv);
    cudaGetSymbolAddress((void**)&pwp, g_wprj);

    cudaFuncSetAttribute(attn_f16, cudaFuncAttributeMaxDynamicSharedMemorySize, ATTN_SMEM);

    conv_kernel<<<(3 * C_ * C_ / 4 + 255) / 256, 256>>>(w_qkv, pwq, 3 * C_ * C_ / 4);
    conv_kernel<<<(C_ * C_ / 4 + 255) / 256, 256>>>(w_proj, pwp, C_ * C_ / 4);
    gn_kernel<<<B_ * NG, 512>>>(x, gamma, beta, ph);
    gemm_f16<<<dim3(8, 12, 16), 256>>>(pwq, ph, b_qkv, nullptr, nullptr, pq);
    attn_f16<<<dim3(16, NH, B_), 128, ATTN_SMEM>>>(pq, pa);
    gemm_f16<<<dim3(8, 4, 16), 256>>>(pwp, pa, b_proj, x, out, nullptr);
}